// round 13
// baseline (speedup 1.0000x reference)
#include <cuda_runtime.h>
#include <cuda_fp16.h>
#include <math.h>
#include <stdint.h>

#define BB 2
#define SS 2048
#define DD 1024
#define HH 16
#define DFF 4096
#define MTOK 4096

// ---------------- scratch (no allocations allowed) ----------------
__device__ __half g_xr[(size_t)MTOK * DD];           // fp16 x
__device__ __half g_WpackT[(size_t)3 * DD * DD];     // [3D, D] K-major packed qkv weights
__device__ float  g_bpack[3 * DD];
__device__ __half g_W1T[(size_t)DFF * DD];           // [4D, D]
__device__ __half g_W2T[(size_t)DD * DFF];           // [D, 4D]
__device__ __half g_QKV[(size_t)MTOK * 3 * DD];      // [tok, 3D] fp16
__device__ float  g_attn[(size_t)MTOK * DD];
__device__ float  g_x1[(size_t)MTOK * DD];           // exact
__device__ __half g_x1r[(size_t)MTOK * DD];          // fp16
__device__ __half g_h1[(size_t)MTOK * DFF];          // fp16
__device__ float  g_ffn[(size_t)MTOK * DD];

// ---------------- helpers ----------------
__device__ __forceinline__ uint32_t smem_u32(const void* p) {
    uint32_t a;
    asm("{ .reg .u64 t; cvta.to.shared.u64 t, %1; cvt.u32.u64 %0, t; }" : "=r"(a) : "l"(p));
    return a;
}
__device__ __forceinline__ uint32_t packh2(float lo, float hi) {
    uint32_t u;
    asm("cvt.rn.f16x2.f32 %0, %1, %2;" : "=r"(u) : "f"(hi), "f"(lo));
    return u;
}
#define SWZ128(o) ((o) ^ (((o) >> 3) & 0x70))
#define CP16(dst, src) asm volatile("cp.async.cg.shared.global [%0], [%1], 16;" :: "r"(dst), "l"(src))
#define LDSM4(r0, r1, r2, r3, a) \
    asm volatile("ldmatrix.sync.aligned.m8n8.x4.shared.b16 {%0,%1,%2,%3}, [%4];" \
                 : "=r"(r0), "=r"(r1), "=r"(r2), "=r"(r3) : "r"(a))
#define LDSM4T(r0, r1, r2, r3, a) \
    asm volatile("ldmatrix.sync.aligned.m8n8.x4.trans.shared.b16 {%0,%1,%2,%3}, [%4];" \
                 : "=r"(r0), "=r"(r1), "=r"(r2), "=r"(r3) : "r"(a))

__device__ __forceinline__ void mma_f16(float* d, const uint32_t* a, uint32_t b0, uint32_t b1) {
    asm volatile(
        "mma.sync.aligned.m16n8k16.row.col.f32.f16.f16.f32 "
        "{%0,%1,%2,%3}, {%4,%5,%6,%7}, {%8,%9}, {%0,%1,%2,%3};"
        : "+f"(d[0]), "+f"(d[1]), "+f"(d[2]), "+f"(d[3])
        : "r"(a[0]), "r"(a[1]), "r"(a[2]), "r"(a[3]), "r"(b0), "r"(b1));
}

// ================= FLASH ATTENTION (fp16, 128 q-rows/CTA) — R8 frozen =================
#define FK_BYTES 16384
#define FV_BYTES 16384
#define OFF_Q 0
#define OFF_K 16384
#define OFF_V 49152
#define OFF_M 81920
#define FA_SMEM 90112

__global__ void __launch_bounds__(256, 1)
flash_attn(const __half* __restrict__ QKV, const int* __restrict__ mask,
           float* __restrict__ out) {
    extern __shared__ char smem[];
    const uint32_t sb = smem_u32(smem);
    int tid = threadIdx.x, wid = tid >> 5, lid = tid & 31;
    int g = lid >> 2, tc = lid & 3;
    int qt = blockIdx.x, bh = blockIdx.y;
    int b = bh >> 4, h = bh & 15;
    int q0 = qt * 128;
    int wq0 = wid * 16;
    const __half* base = QKV + (size_t)b * SS * 3072 + h * 64;

    int rA = (lid & 7) + ((lid >> 3) & 1) * 8;
    int cA = lid >> 4;
    int rB = (lid & 7) + ((lid >> 4) & 1) * 8;
    int cB = (lid >> 3) & 1;

#pragma unroll
    for (int i = 0; i < 4; i++) {
        int q = tid + i * 256, r = q >> 3, c = q & 7;
        CP16(sb + OFF_Q + SWZ128(q * 16), base + (size_t)(q0 + r) * 3072 + c * 8);
    }
#pragma unroll
    for (int i = 0; i < 4; i++) {
        int q = tid + i * 256, r = q >> 3, c = q & 7;
        CP16(sb + OFF_K + SWZ128(q * 16), base + (size_t)r * 3072 + 1024 + c * 8);
    }
#pragma unroll
    for (int i = 0; i < 4; i++) {
        int q = tid + i * 256, r = q >> 3, c = q & 7;
        CP16(sb + OFF_V + SWZ128(q * 16), base + (size_t)r * 3072 + 2048 + c * 8);
    }
    asm volatile("cp.async.commit_group;" ::: "memory");
    int* msmem = (int*)(smem + OFF_M);
#pragma unroll
    for (int i = 0; i < 8; i++) {
        int idx = tid + i * 256;
        msmem[idx] = mask[b * SS + idx];
    }
    asm volatile("cp.async.wait_group 0;" ::: "memory");
    __syncthreads();

    uint32_t af[4][4];
#pragma unroll
    for (int s = 0; s < 4; s++) {
        uint32_t addr = sb + OFF_Q + SWZ128((wq0 + rA) * 128 + (2 * s + cA) * 16);
        LDSM4(af[s][0], af[s][1], af[s][2], af[s][3], addr);
    }

    float oacc[8][4];
#pragma unroll
    for (int i = 0; i < 8; i++)
#pragma unroll
        for (int j = 0; j < 4; j++) oacc[i][j] = 0.f;
    float l0 = 0.f, l1 = 0.f, m0 = -INFINITY, m1 = -INFINITY;

    for (int it = 0; it < 16; it++) {
        int buf = it & 1;
        if (it + 1 < 16) {
            int kv1 = (it + 1) * 128, nb = buf ^ 1;
#pragma unroll
            for (int i = 0; i < 4; i++) {
                int q = tid + i * 256, r = q >> 3, c = q & 7;
                CP16(sb + OFF_K + nb * FK_BYTES + SWZ128(q * 16),
                     base + (size_t)(kv1 + r) * 3072 + 1024 + c * 8);
            }
#pragma unroll
            for (int i = 0; i < 4; i++) {
                int q = tid + i * 256, r = q >> 3, c = q & 7;
                CP16(sb + OFF_V + nb * FV_BYTES + SWZ128(q * 16),
                     base + (size_t)(kv1 + r) * 3072 + 2048 + c * 8);
            }
            asm volatile("cp.async.commit_group;" ::: "memory");
        }
        if (it > 0) {
            if (it + 1 < 16) asm volatile("cp.async.wait_group 1;" ::: "memory");
            else             asm volatile("cp.async.wait_group 0;" ::: "memory");
            __syncthreads();
        }

        int kv0 = it * 128;
        uint32_t kb = sb + OFF_K + buf * FK_BYTES;
        uint32_t vb = sb + OFF_V + buf * FV_BYTES;

        float sacc[16][4];
#pragma unroll
        for (int i = 0; i < 16; i++)
#pragma unroll
            for (int j = 0; j < 4; j++) sacc[i][j] = 0.f;
#pragma unroll
        for (int np = 0; np < 8; np++) {
            int nrow = 16 * np + rB;
#pragma unroll
            for (int s = 0; s < 4; s++) {
                uint32_t bq[4];
                LDSM4(bq[0], bq[1], bq[2], bq[3],
                      kb + SWZ128(nrow * 128 + (2 * s + cB) * 16));
                mma_f16(sacc[2 * np],     af[s], bq[0], bq[1]);
                mma_f16(sacc[2 * np + 1], af[s], bq[2], bq[3]);
            }
        }

        float mt0 = -INFINITY, mt1 = -INFINITY;
#pragma unroll
        for (int nt = 0; nt < 16; nt++) {
            int c0 = kv0 + 8 * nt + 2 * tc;
            int mk0 = msmem[c0], mk1 = msmem[c0 + 1];
            float s0 = sacc[nt][0] * 0.125f, s1 = sacc[nt][1] * 0.125f;
            float s2 = sacc[nt][2] * 0.125f, s3 = sacc[nt][3] * 0.125f;
            if (mk0 == 0) { s0 = -INFINITY; s2 = -INFINITY; }
            if (mk1 == 0) { s1 = -INFINITY; s3 = -INFINITY; }
            sacc[nt][0] = s0; sacc[nt][1] = s1; sacc[nt][2] = s2; sacc[nt][3] = s3;
            mt0 = fmaxf(mt0, fmaxf(s0, s1));
            mt1 = fmaxf(mt1, fmaxf(s2, s3));
        }
        mt0 = fmaxf(mt0, __shfl_xor_sync(0xffffffff, mt0, 1));
        mt0 = fmaxf(mt0, __shfl_xor_sync(0xffffffff, mt0, 2));
        mt1 = fmaxf(mt1, __shfl_xor_sync(0xffffffff, mt1, 1));
        mt1 = fmaxf(mt1, __shfl_xor_sync(0xffffffff, mt1, 2));
        float mn0 = fmaxf(m0, mt0), mn1 = fmaxf(m1, mt1);
        float al0 = __expf(m0 - mn0), al1 = __expf(m1 - mn1);
        l0 *= al0; l1 *= al1;
#pragma unroll
        for (int i = 0; i < 8; i++) {
            oacc[i][0] *= al0; oacc[i][1] *= al0;
            oacc[i][2] *= al1; oacc[i][3] *= al1;
        }
#pragma unroll
        for (int nt = 0; nt < 16; nt++) {
            float p0 = __expf(sacc[nt][0] - mn0);
            float p1 = __expf(sacc[nt][1] - mn0);
            float p2 = __expf(sacc[nt][2] - mn1);
            float p3 = __expf(sacc[nt][3] - mn1);
            l0 += p0 + p1; l1 += p2 + p3;
            sacc[nt][0] = p0; sacc[nt][1] = p1;
            sacc[nt][2] = p2; sacc[nt][3] = p3;
        }
        m0 = mn0; m1 = mn1;

#pragma unroll
        for (int kc = 0; kc < 8; kc++) {
            uint32_t afr[4];
            afr[0] = packh2(sacc[2 * kc][0],     sacc[2 * kc][1]);
            afr[1] = packh2(sacc[2 * kc][2],     sacc[2 * kc][3]);
            afr[2] = packh2(sacc[2 * kc + 1][0], sacc[2 * kc + 1][1]);
            afr[3] = packh2(sacc[2 * kc + 1][2], sacc[2 * kc + 1][3]);
            int vrow = 16 * kc + rA;
#pragma unroll
            for (int np = 0; np < 4; np++) {
                uint32_t bv[4];
                LDSM4T(bv[0], bv[1], bv[2], bv[3],
                       vb + SWZ128(vrow * 128 + np * 32 + cA * 16));
                mma_f16(oacc[2 * np],     afr, bv[0], bv[1]);
                mma_f16(oacc[2 * np + 1], afr, bv[2], bv[3]);
            }
        }
        __syncthreads();
    }

    l0 += __shfl_xor_sync(0xffffffff, l0, 1);
    l0 += __shfl_xor_sync(0xffffffff, l0, 2);
    l1 += __shfl_xor_sync(0xffffffff, l1, 1);
    l1 += __shfl_xor_sync(0xffffffff, l1, 2);

    float il0 = 1.f / l0, il1 = 1.f / l1;
    int r0 = q0 + wq0 + g, r1 = r0 + 8;
    float* o0 = out + (size_t)(b * SS + r0) * DD + h * 64 + 2 * tc;
    float* o1 = out + (size_t)(b * SS + r1) * DD + h * 64 + 2 * tc;
#pragma unroll
    for (int nt = 0; nt < 8; nt++) {
        *(float2*)(o0 + nt * 8) = make_float2(oacc[nt][0] * il0, oacc[nt][1] * il0);
        *(float2*)(o1 + nt * 8) = make_float2(oacc[nt][2] * il1, oacc[nt][3] * il1);
    }
}

// ---------------- fp16 mma GEMM: 256x128 tile, BK=64, 512 threads, 3-stage ----------------
#define GA_BYTES 32768
#define GB_BYTES 16384
#define G_SMEM (3 * GA_BYTES + 3 * GB_BYTES)

template <int MODE, bool WH>
__global__ void __launch_bounds__(512)
mma_gemm(const __half* __restrict__ A, int lda,
         const __half* __restrict__ B, int ldb,
         void* __restrict__ Cv, int ldc,
         const float* __restrict__ bias, int K) {
    extern __shared__ char smem[];
    const uint32_t sb = smem_u32(smem);
    int tid = threadIdx.x, wid = tid >> 5, lid = tid & 31;
    int m0 = blockIdx.y * 256, n0 = blockIdx.x * 128;
    int wm0 = (wid >> 2) * 64, wn0 = (wid & 3) * 32;

    int rA = (lid & 7) + ((lid >> 3) & 1) * 8;
    int cA = lid >> 4;
    int rB = (lid & 7) + ((lid >> 4) & 1) * 8;
    int cB = (lid >> 3) & 1;

    float acc[4][4][4];
#pragma unroll
    for (int i = 0; i < 4; i++)
#pragma unroll
        for (int j = 0; j < 4; j++)
#pragma unroll
            for (int r = 0; r < 4; r++) acc[i][j][r] = 0.f;

    const int NC = K >> 6;

#pragma unroll
    for (int pc = 0; pc < 2; pc++) {
        int k0 = pc << 6;
        uint32_t ab = sb + pc * GA_BYTES;
        uint32_t bb = sb + 3 * GA_BYTES + pc * GB_BYTES;
#pragma unroll
        for (int i = 0; i < 4; i++) {
            int q = tid + i * 512, row = q >> 3, cg = q & 7;
            CP16(ab + SWZ128(q * 16), A + (size_t)(m0 + row) * lda + k0 + cg * 8);
        }
#pragma unroll
        for (int i = 0; i < 2; i++) {
            int q = tid + i * 512, row = q >> 3, cg = q & 7;
            CP16(bb + SWZ128(q * 16), B + (size_t)(n0 + row) * ldb + k0 + cg * 8);
        }
        asm volatile("cp.async.commit_group;" ::: "memory");
    }

    for (int c = 0; c < NC; c++) {
        int buf = c % 3;
        __syncthreads();
        if (c + 2 < NC) {
            int k0 = (c + 2) << 6;
            int lb = (c + 2) % 3;
            uint32_t ab = sb + lb * GA_BYTES;
            uint32_t bb = sb + 3 * GA_BYTES + lb * GB_BYTES;
#pragma unroll
            for (int i = 0; i < 4; i++) {
                int q = tid + i * 512, row = q >> 3, cg = q & 7;
                CP16(ab + SWZ128(q * 16), A + (size_t)(m0 + row) * lda + k0 + cg * 8);
            }
#pragma unroll
            for (int i = 0; i < 2; i++) {
                int q = tid + i * 512, row = q >> 3, cg = q & 7;
                CP16(bb + SWZ128(q * 16), B + (size_t)(n0 + row) * ldb + k0 + cg * 8);
            }
            asm volatile("cp.async.commit_group;" ::: "memory");
        }
        int rem = NC - 1 - c;
        if (rem >= 2)      asm volatile("cp.async.wait_group 2;" ::: "memory");
        else if (rem == 1) asm volatile("cp.async.wait_group 1;" ::: "memory");
        else               asm volatile("cp.async.wait_group 0;" ::: "memory");
        __syncthreads();

        uint32_t ab = sb + buf * GA_BYTES;
        uint32_t bb = sb + 3 * GA_BYTES + buf * GB_BYTES;
#pragma unroll
        for (int s = 0; s < 4; s++) {
            uint32_t af[4][4];
#pragma unroll
            for (int mt = 0; mt < 4; mt++) {
                int row = wm0 + mt * 16 + rA;
                LDSM4(af[mt][0], af[mt][1], af[mt][2], af[mt][3],
                      ab + SWZ128(row * 128 + (2 * s + cA) * 16));
            }
            uint32_t bfr[8];
#pragma unroll
            for (int pr = 0; pr < 2; pr++) {
                int row = wn0 + pr * 16 + rB;
                LDSM4(bfr[4 * pr], bfr[4 * pr + 1], bfr[4 * pr + 2], bfr[4 * pr + 3],
                      bb + SWZ128(row * 128 + (2 * s + cB) * 16));
            }
#pragma unroll
            for (int mt = 0; mt < 4; mt++) {
#pragma unroll
                for (int nt = 0; nt < 4; nt++)
                    mma_f16(acc[mt][nt], af[mt], bfr[2 * nt], bfr[2 * nt + 1]);
            }
        }
    }

    int g = lid >> 2, tc = lid & 3;
#pragma unroll
    for (int mt = 0; mt < 4; mt++) {
        int row = m0 + wm0 + mt * 16 + g;
#pragma unroll
        for (int nt = 0; nt < 4; nt++) {
            int col = n0 + wn0 + nt * 8 + tc * 2;
            float v00 = acc[mt][nt][0], v01 = acc[mt][nt][1];
            float v10 = acc[mt][nt][2], v11 = acc[mt][nt][3];
            float2 bv = *(const float2*)(bias + col);
            v00 += bv.x; v01 += bv.y; v10 += bv.x; v11 += bv.y;
            if (MODE == 1) {
                v00 = fmaxf(v00, 0.f); v01 = fmaxf(v01, 0.f);
                v10 = fmaxf(v10, 0.f); v11 = fmaxf(v11, 0.f);
            }
            if (WH) {
                __half* C = (__half*)Cv;
                *(uint32_t*)(C + (size_t)row * ldc + col) = packh2(v00, v01);
                *(uint32_t*)(C + (size_t)(row + 8) * ldc + col) = packh2(v10, v11);
            } else {
                float* C = (float*)Cv;
                *(float2*)(C + (size_t)row * ldc + col) = make_float2(v00, v01);
                *(float2*)(C + (size_t)(row + 8) * ldc + col) = make_float2(v10, v11);
            }
        }
    }
}

// ---------------- fused prep ----------------
__global__ void prep_all(const float* __restrict__ x,
                         const float* __restrict__ Wq, const float* __restrict__ Wk,
                         const float* __restrict__ Wv,
                         const float* __restrict__ bq, const float* __restrict__ bk,
                         const float* __restrict__ bv,
                         const float* __restrict__ W1, const float* __restrict__ W2) {
    __shared__ float t[32][33];
    int bid = blockIdx.x;
    int tid = threadIdx.x;
    int tx = tid & 31, ty = tid >> 5;

    if (bid < 4096) {
        int i = bid * 256 + tid;
        float4 v = ((const float4*)x)[i];
        uint32_t* o = (uint32_t*)g_xr;
        o[2 * i]     = packh2(v.x, v.y);
        o[2 * i + 1] = packh2(v.z, v.w);
    } else if (bid < 4108) {
        int i = (bid - 4096) * 256 + tid;
        if (i < 3 * DD) {
            int which = i / DD, c = i % DD;
            const float* b = (which == 0) ? bq : (which == 1) ? bk : bv;
            g_bpack[i] = b[c];
        }
    } else if (bid < 7180) {
        int z = bid - 4108;
        int bx = z & 31;
        int by = (z >> 5) & 1;
        int bz = z >> 6;
        int which = bz / HH, h = bz % HH;
        const float* W = (which == 0) ? Wq : (which == 1) ? Wk : Wv;
        int d0 = bx * 32, e0 = by * 32;
#pragma unroll
        for (int i = 0; i < 32; i += 8)
            t[ty + i][tx] = W[(size_t)h * (DD * 64) + (size_t)(d0 + ty + i) * 64 + e0 + tx];
        __syncthreads();
#pragma unroll
        for (int i = 0; i < 32; i += 8)
            g_WpackT[(size_t)(which * DD + h * 64 + e0 + ty + i) * DD + d0 + tx] =
                __float2half_rn(t[tx][ty + i]);
    } else if (bid < 11276) {
        int z = bid - 7180;
        int bx = z & 127;
        int by = z >> 7;
        int c0 = bx * 32, r0 = by * 32;
#pragma unroll
        for (int i = 0; i < 32; i += 8)
            t[ty + i][tx] = W1[(size_t)(r0 + ty + i) * DFF + c0 + tx];
        __syncthreads();
#pragma unroll
        for (int i = 0; i < 32; i += 8)
            g_W1T[(size_t)(c0 + ty + i) * DD + r0 + tx] = __float2half_rn(t[tx][ty + i]);
    } else {
        int z = bid - 11276;
        int bx = z & 31;
        int by = z >> 5;
        int c0 = bx * 32, r0 = by * 32;
#pragma unroll
        for (int i = 0; i < 32; i += 8)
            t[ty + i][tx] = W2[(size_t)(r0 + ty + i) * DD + c0 + tx];
        __syncthreads();
#pragma unroll
        for (int i = 0; i < 32; i += 8)
            g_W2T[(size_t)(c0 + ty + i) * DFF + r0 + tx] = __float2half_rn(t[tx][ty + i]);
    }
}

// ---------------- out = xres + alpha*(a-mean)/(std_unbiased+eps) + beta ----------------
// one row per WARP: warp-local shuffle reduction, MLP=8 loads, no barriers
template <bool DUAL>
__global__ void __launch_bounds__(256)
add_ln(const float* __restrict__ xres, const float* __restrict__ a,
       const float* __restrict__ alpha, const float* __restrict__ beta,
       float* __restrict__ out, __half* __restrict__ outr) {
    int wid = threadIdx.x >> 5, lid = threadIdx.x & 31;
    int row = blockIdx.x * 8 + wid;

    const float4* ap = (const float4*)(a + (size_t)row * DD);
    float4 v[8];
#pragma unroll
    for (int i = 0; i < 8; i++) v[i] = ap[lid + i * 32];

    float s = 0.f, sq = 0.f;
#pragma unroll
    for (int i = 0; i < 8; i++) {
        s  += (v[i].x + v[i].y) + (v[i].z + v[i].w);
        sq += v[i].x * v[i].x + v[i].y * v[i].y + v[i].z * v[i].z + v[i].w * v[i].w;
    }
#pragma unroll
    for (int o = 16; o > 0; o >>= 1) {
        s  += __shfl_xor_sync(0xffffffff, s, o);
        sq += __shfl_xor_sync(0xffffffff, sq, o);
    }
    float mean = s * (1.f / DD);
    float var = (sq - (float)DD * mean * mean) * (1.f / (DD - 1));
    float inv = 1.f / (sqrtf(fmaxf(var, 0.f)) + 1e-6f);

    const float4* xp = (const float4*)(xres + (size_t)row * DD);
    const float4* alp = (const float4*)alpha;
    const float4* bep = (const float4*)beta;
    float4* op = (float4*)(out + (size_t)row * DD);
    uint32_t* oh = DUAL ? (uint32_t*)(outr + (size_t)row * DD) : nullptr;
#pragma unroll
    for (int i = 0; i < 8; i++) {
        int c = lid + i * 32;
        float4 xr4 = xp[c];
        float4 al4 = alp[c];
        float4 be4 = bep[c];
        float4 o4;
        o4.x = xr4.x + al4.x * (v[i].x - mean) * inv + be4.x;
        o4.y = xr4.y + al4.y * (v[i].y - mean) * inv + be4.y;
        o4.z = xr4.z + al4.z * (v[i].z - mean) * inv + be4.z;
        o4.w = xr4.w + al4.w * (v[i].w - mean) * inv + be4.w;
        op[c] = o4;
        if (DUAL) {
            oh[2 * c]     = packh2(o4.x, o4.y);
            oh[2 * c + 1] = packh2(o4.z, o4.w);
        }
    }
}

// ---------------- launch ----------------
extern "C" void kernel_launch(void* const* d_in, const int* in_sizes, int n_in,
                              void* d_out, int out_size) {
    const float* x      = (const float*)d_in[0];
    const int*   mask   = (const int*)d_in[1];
    const float* Wq     = (const float*)d_in[2];
    const float* bq     = (const float*)d_in[3];
    const float* Wk     = (const float*)d_in[4];
    const float* bk     = (const float*)d_in[5];
    const float* Wv     = (const float*)d_in[6];
    const float* bv     = (const float*)d_in[7];
    const float* W1     = (const float*)d_in[8];
    const float* b1     = (const float*)d_in[9];
    const float* W2     = (const float*)d_in[10];
    const float* b2     = (const float*)d_in[11];
    const float* alpha1 = (const float*)d_in[12];
    const float* beta1  = (const float*)d_in[13];
    const float* alpha2 = (const float*)d_in[14];
    const float* beta2  = (const float*)d_in[15];
    float* out = (float*)d_out;

    __half *xr, *WpackT, *W1T, *W2T, *QKV, *x1r, *h1;
    float *bpack, *attn, *x1, *ffn;
    cudaGetSymbolAddress((void**)&xr,     g_xr);
    cudaGetSymbolAddress((void**)&WpackT, g_WpackT);
    cudaGetSymbolAddress((void**)&bpack,  g_bpack);
    cudaGetSymbolAddress((void**)&W1T,    g_W1T);
    cudaGetSymbolAddress((void**)&W2T,    g_W2T);
    cudaGetSymbolAddress((void**)&QKV,    g_QKV);
    cudaGetSymbolAddress((void**)&attn,   g_attn);
    cudaGetSymbolAddress((void**)&x1,     g_x1);
    cudaGetSymbolAddress((void**)&x1r,    g_x1r);
    cudaGetSymbolAddress((void**)&h1,     g_h1);
    cudaGetSymbolAddress((void**)&ffn,    g_ffn);

    cudaFuncSetAttribute(mma_gemm<0, true>,  cudaFuncAttributeMaxDynamicSharedMemorySize, G_SMEM);
    cudaFuncSetAttribute(mma_gemm<1, true>,  cudaFuncAttributeMaxDynamicSharedMemorySize, G_SMEM);
    cudaFuncSetAttribute(mma_gemm<0, false>, cudaFuncAttributeMaxDynamicSharedMemorySize, G_SMEM);
    cudaFuncSetAttribute(flash_attn, cudaFuncAttributeMaxDynamicSharedMemorySize, FA_SMEM);

    // fused prep (one launch)
    prep_all<<<15372, 256>>>(x, Wq, Wk, Wv, bq, bk, bv, W1, W2);

    // QKV = xr @ WpackT^T + bias  [4096, 3072] fp16 out
    mma_gemm<0, true><<<dim3(24, 16), 512, G_SMEM>>>(
        xr, DD, WpackT, DD, QKV, 3 * DD, bpack, DD);

    // fused attention: scores + mask + softmax + P@V (fp16 mma, fp32 out)
    flash_attn<<<dim3(16, 32), 256, FA_SMEM>>>(QKV, mask, attn);

    // x1 = x + LN1(attn)  (fp32 + fp16 copy)
    add_ln<true><<<MTOK / 8, 256>>>(x, attn, alpha1, beta1, x1, x1r);

    // FFN1: relu(x1r @ W1 + b1) fp16 out
    mma_gemm<1, true><<<dim3(32, 16), 512, G_SMEM>>>(
        x1r, DD, W1T, DD, h1, DFF, b1, DD);

    // FFN2: h1 @ W2 + b2  fp32 out
    mma_gemm<0, false><<<dim3(8, 16), 512, G_SMEM>>>(
        h1, DFF, W2T, DFF, ffn, DD, b2, DFF);

    // out = x1 + LN2(ffn)
    add_ln<false><<<MTOK / 8, 256>>>(x1, ffn, alpha2, beta2, out, nullptr);
}

// round 14
// speedup vs baseline: 1.0041x; 1.0041x over previous
#include <cuda_runtime.h>
#include <cuda_fp16.h>
#include <math.h>
#include <stdint.h>

#define BB 2
#define SS 2048
#define DD 1024
#define HH 16
#define DFF 4096
#define MTOK 4096

// ---------------- scratch (no allocations allowed) ----------------
__device__ __half g_xr[(size_t)MTOK * DD];           // fp16 x
__device__ __half g_WpackT[(size_t)3 * DD * DD];     // [3D, D] K-major packed qkv weights
__device__ float  g_bpack[3 * DD];
__device__ __half g_W1T[(size_t)DFF * DD];           // [4D, D]
__device__ __half g_W2T[(size_t)DD * DFF];           // [D, 4D]
__device__ __half g_QKV[(size_t)MTOK * 3 * DD];      // [tok, 3D] fp16
__device__ float  g_attn[(size_t)MTOK * DD];
__device__ float  g_x1[(size_t)MTOK * DD];           // exact
__device__ __half g_x1r[(size_t)MTOK * DD];          // fp16
__device__ __half g_h1[(size_t)MTOK * DFF];          // fp16
__device__ float  g_ffn[(size_t)MTOK * DD];

// ---------------- helpers ----------------
__device__ __forceinline__ uint32_t smem_u32(const void* p) {
    uint32_t a;
    asm("{ .reg .u64 t; cvta.to.shared.u64 t, %1; cvt.u32.u64 %0, t; }" : "=r"(a) : "l"(p));
    return a;
}
__device__ __forceinline__ uint32_t packh2(float lo, float hi) {
    uint32_t u;
    asm("cvt.rn.f16x2.f32 %0, %1, %2;" : "=r"(u) : "f"(hi), "f"(lo));
    return u;
}
#define SWZ128(o) ((o) ^ (((o) >> 3) & 0x70))
#define CP16(dst, src) asm volatile("cp.async.cg.shared.global [%0], [%1], 16;" :: "r"(dst), "l"(src))
#define LDSM4(r0, r1, r2, r3, a) \
    asm volatile("ldmatrix.sync.aligned.m8n8.x4.shared.b16 {%0,%1,%2,%3}, [%4];" \
                 : "=r"(r0), "=r"(r1), "=r"(r2), "=r"(r3) : "r"(a))
#define LDSM4T(r0, r1, r2, r3, a) \
    asm volatile("ldmatrix.sync.aligned.m8n8.x4.trans.shared.b16 {%0,%1,%2,%3}, [%4];" \
                 : "=r"(r0), "=r"(r1), "=r"(r2), "=r"(r3) : "r"(a))

__device__ __forceinline__ void mma_f16(float* d, const uint32_t* a, uint32_t b0, uint32_t b1) {
    asm volatile(
        "mma.sync.aligned.m16n8k16.row.col.f32.f16.f16.f32 "
        "{%0,%1,%2,%3}, {%4,%5,%6,%7}, {%8,%9}, {%0,%1,%2,%3};"
        : "+f"(d[0]), "+f"(d[1]), "+f"(d[2]), "+f"(d[3])
        : "r"(a[0]), "r"(a[1]), "r"(a[2]), "r"(a[3]), "r"(b0), "r"(b1));
}

// ================= FLASH ATTENTION (fp16, 128 q-rows/CTA) — R8 frozen =================
#define FK_BYTES 16384
#define FV_BYTES 16384
#define OFF_Q 0
#define OFF_K 16384
#define OFF_V 49152
#define OFF_M 81920
#define FA_SMEM 90112

__global__ void __launch_bounds__(256, 1)
flash_attn(const __half* __restrict__ QKV, const int* __restrict__ mask,
           float* __restrict__ out) {
    extern __shared__ char smem[];
    const uint32_t sb = smem_u32(smem);
    int tid = threadIdx.x, wid = tid >> 5, lid = tid & 31;
    int g = lid >> 2, tc = lid & 3;
    int qt = blockIdx.x, bh = blockIdx.y;
    int b = bh >> 4, h = bh & 15;
    int q0 = qt * 128;
    int wq0 = wid * 16;
    const __half* base = QKV + (size_t)b * SS * 3072 + h * 64;

    int rA = (lid & 7) + ((lid >> 3) & 1) * 8;
    int cA = lid >> 4;
    int rB = (lid & 7) + ((lid >> 4) & 1) * 8;
    int cB = (lid >> 3) & 1;

#pragma unroll
    for (int i = 0; i < 4; i++) {
        int q = tid + i * 256, r = q >> 3, c = q & 7;
        CP16(sb + OFF_Q + SWZ128(q * 16), base + (size_t)(q0 + r) * 3072 + c * 8);
    }
#pragma unroll
    for (int i = 0; i < 4; i++) {
        int q = tid + i * 256, r = q >> 3, c = q & 7;
        CP16(sb + OFF_K + SWZ128(q * 16), base + (size_t)r * 3072 + 1024 + c * 8);
    }
#pragma unroll
    for (int i = 0; i < 4; i++) {
        int q = tid + i * 256, r = q >> 3, c = q & 7;
        CP16(sb + OFF_V + SWZ128(q * 16), base + (size_t)r * 3072 + 2048 + c * 8);
    }
    asm volatile("cp.async.commit_group;" ::: "memory");
    int* msmem = (int*)(smem + OFF_M);
#pragma unroll
    for (int i = 0; i < 8; i++) {
        int idx = tid + i * 256;
        msmem[idx] = mask[b * SS + idx];
    }
    asm volatile("cp.async.wait_group 0;" ::: "memory");
    __syncthreads();

    uint32_t af[4][4];
#pragma unroll
    for (int s = 0; s < 4; s++) {
        uint32_t addr = sb + OFF_Q + SWZ128((wq0 + rA) * 128 + (2 * s + cA) * 16);
        LDSM4(af[s][0], af[s][1], af[s][2], af[s][3], addr);
    }

    float oacc[8][4];
#pragma unroll
    for (int i = 0; i < 8; i++)
#pragma unroll
        for (int j = 0; j < 4; j++) oacc[i][j] = 0.f;
    float l0 = 0.f, l1 = 0.f, m0 = -INFINITY, m1 = -INFINITY;

    for (int it = 0; it < 16; it++) {
        int buf = it & 1;
        if (it + 1 < 16) {
            int kv1 = (it + 1) * 128, nb = buf ^ 1;
#pragma unroll
            for (int i = 0; i < 4; i++) {
                int q = tid + i * 256, r = q >> 3, c = q & 7;
                CP16(sb + OFF_K + nb * FK_BYTES + SWZ128(q * 16),
                     base + (size_t)(kv1 + r) * 3072 + 1024 + c * 8);
            }
#pragma unroll
            for (int i = 0; i < 4; i++) {
                int q = tid + i * 256, r = q >> 3, c = q & 7;
                CP16(sb + OFF_V + nb * FV_BYTES + SWZ128(q * 16),
                     base + (size_t)(kv1 + r) * 3072 + 2048 + c * 8);
            }
            asm volatile("cp.async.commit_group;" ::: "memory");
        }
        if (it > 0) {
            if (it + 1 < 16) asm volatile("cp.async.wait_group 1;" ::: "memory");
            else             asm volatile("cp.async.wait_group 0;" ::: "memory");
            __syncthreads();
        }

        int kv0 = it * 128;
        uint32_t kb = sb + OFF_K + buf * FK_BYTES;
        uint32_t vb = sb + OFF_V + buf * FV_BYTES;

        float sacc[16][4];
#pragma unroll
        for (int i = 0; i < 16; i++)
#pragma unroll
            for (int j = 0; j < 4; j++) sacc[i][j] = 0.f;
#pragma unroll
        for (int np = 0; np < 8; np++) {
            int nrow = 16 * np + rB;
#pragma unroll
            for (int s = 0; s < 4; s++) {
                uint32_t bq[4];
                LDSM4(bq[0], bq[1], bq[2], bq[3],
                      kb + SWZ128(nrow * 128 + (2 * s + cB) * 16));
                mma_f16(sacc[2 * np],     af[s], bq[0], bq[1]);
                mma_f16(sacc[2 * np + 1], af[s], bq[2], bq[3]);
            }
        }

        float mt0 = -INFINITY, mt1 = -INFINITY;
#pragma unroll
        for (int nt = 0; nt < 16; nt++) {
            int c0 = kv0 + 8 * nt + 2 * tc;
            int mk0 = msmem[c0], mk1 = msmem[c0 + 1];
            float s0 = sacc[nt][0] * 0.125f, s1 = sacc[nt][1] * 0.125f;
            float s2 = sacc[nt][2] * 0.125f, s3 = sacc[nt][3] * 0.125f;
            if (mk0 == 0) { s0 = -INFINITY; s2 = -INFINITY; }
            if (mk1 == 0) { s1 = -INFINITY; s3 = -INFINITY; }
            sacc[nt][0] = s0; sacc[nt][1] = s1; sacc[nt][2] = s2; sacc[nt][3] = s3;
            mt0 = fmaxf(mt0, fmaxf(s0, s1));
            mt1 = fmaxf(mt1, fmaxf(s2, s3));
        }
        mt0 = fmaxf(mt0, __shfl_xor_sync(0xffffffff, mt0, 1));
        mt0 = fmaxf(mt0, __shfl_xor_sync(0xffffffff, mt0, 2));
        mt1 = fmaxf(mt1, __shfl_xor_sync(0xffffffff, mt1, 1));
        mt1 = fmaxf(mt1, __shfl_xor_sync(0xffffffff, mt1, 2));
        float mn0 = fmaxf(m0, mt0), mn1 = fmaxf(m1, mt1);
        float al0 = __expf(m0 - mn0), al1 = __expf(m1 - mn1);
        l0 *= al0; l1 *= al1;
#pragma unroll
        for (int i = 0; i < 8; i++) {
            oacc[i][0] *= al0; oacc[i][1] *= al0;
            oacc[i][2] *= al1; oacc[i][3] *= al1;
        }
#pragma unroll
        for (int nt = 0; nt < 16; nt++) {
            float p0 = __expf(sacc[nt][0] - mn0);
            float p1 = __expf(sacc[nt][1] - mn0);
            float p2 = __expf(sacc[nt][2] - mn1);
            float p3 = __expf(sacc[nt][3] - mn1);
            l0 += p0 + p1; l1 += p2 + p3;
            sacc[nt][0] = p0; sacc[nt][1] = p1;
            sacc[nt][2] = p2; sacc[nt][3] = p3;
        }
        m0 = mn0; m1 = mn1;

#pragma unroll
        for (int kc = 0; kc < 8; kc++) {
            uint32_t afr[4];
            afr[0] = packh2(sacc[2 * kc][0],     sacc[2 * kc][1]);
            afr[1] = packh2(sacc[2 * kc][2],     sacc[2 * kc][3]);
            afr[2] = packh2(sacc[2 * kc + 1][0], sacc[2 * kc + 1][1]);
            afr[3] = packh2(sacc[2 * kc + 1][2], sacc[2 * kc + 1][3]);
            int vrow = 16 * kc + rA;
#pragma unroll
            for (int np = 0; np < 4; np++) {
                uint32_t bv[4];
                LDSM4T(bv[0], bv[1], bv[2], bv[3],
                       vb + SWZ128(vrow * 128 + np * 32 + cA * 16));
                mma_f16(oacc[2 * np],     afr, bv[0], bv[1]);
                mma_f16(oacc[2 * np + 1], afr, bv[2], bv[3]);
            }
        }
        __syncthreads();
    }

    l0 += __shfl_xor_sync(0xffffffff, l0, 1);
    l0 += __shfl_xor_sync(0xffffffff, l0, 2);
    l1 += __shfl_xor_sync(0xffffffff, l1, 1);
    l1 += __shfl_xor_sync(0xffffffff, l1, 2);

    float il0 = 1.f / l0, il1 = 1.f / l1;
    int r0 = q0 + wq0 + g, r1 = r0 + 8;
    float* o0 = out + (size_t)(b * SS + r0) * DD + h * 64 + 2 * tc;
    float* o1 = out + (size_t)(b * SS + r1) * DD + h * 64 + 2 * tc;
#pragma unroll
    for (int nt = 0; nt < 8; nt++) {
        *(float2*)(o0 + nt * 8) = make_float2(oacc[nt][0] * il0, oacc[nt][1] * il0);
        *(float2*)(o1 + nt * 8) = make_float2(oacc[nt][2] * il1, oacc[nt][3] * il1);
    }
}

// ---------------- fp16 mma GEMM: 256x128 tile, BK=64, 512 threads, 3-stage ----------------
#define GA_BYTES 32768
#define GB_BYTES 16384
#define G_SMEM (3 * GA_BYTES + 3 * GB_BYTES)

template <int MODE, bool WH>
__global__ void __launch_bounds__(512)
mma_gemm(const __half* __restrict__ A, int lda,
         const __half* __restrict__ B, int ldb,
         void* __restrict__ Cv, int ldc,
         const float* __restrict__ bias, int K) {
    extern __shared__ char smem[];
    const uint32_t sb = smem_u32(smem);
    int tid = threadIdx.x, wid = tid >> 5, lid = tid & 31;
    int m0 = blockIdx.y * 256, n0 = blockIdx.x * 128;
    int wm0 = (wid >> 2) * 64, wn0 = (wid & 3) * 32;

    int rA = (lid & 7) + ((lid >> 3) & 1) * 8;
    int cA = lid >> 4;
    int rB = (lid & 7) + ((lid >> 4) & 1) * 8;
    int cB = (lid >> 3) & 1;

    float acc[4][4][4];
#pragma unroll
    for (int i = 0; i < 4; i++)
#pragma unroll
        for (int j = 0; j < 4; j++)
#pragma unroll
            for (int r = 0; r < 4; r++) acc[i][j][r] = 0.f;

    const int NC = K >> 6;

#pragma unroll
    for (int pc = 0; pc < 2; pc++) {
        int k0 = pc << 6;
        uint32_t ab = sb + pc * GA_BYTES;
        uint32_t bb = sb + 3 * GA_BYTES + pc * GB_BYTES;
#pragma unroll
        for (int i = 0; i < 4; i++) {
            int q = tid + i * 512, row = q >> 3, cg = q & 7;
            CP16(ab + SWZ128(q * 16), A + (size_t)(m0 + row) * lda + k0 + cg * 8);
        }
#pragma unroll
        for (int i = 0; i < 2; i++) {
            int q = tid + i * 512, row = q >> 3, cg = q & 7;
            CP16(bb + SWZ128(q * 16), B + (size_t)(n0 + row) * ldb + k0 + cg * 8);
        }
        asm volatile("cp.async.commit_group;" ::: "memory");
    }

    for (int c = 0; c < NC; c++) {
        int buf = c % 3;
        __syncthreads();
        if (c + 2 < NC) {
            int k0 = (c + 2) << 6;
            int lb = (c + 2) % 3;
            uint32_t ab = sb + lb * GA_BYTES;
            uint32_t bb = sb + 3 * GA_BYTES + lb * GB_BYTES;
#pragma unroll
            for (int i = 0; i < 4; i++) {
                int q = tid + i * 512, row = q >> 3, cg = q & 7;
                CP16(ab + SWZ128(q * 16), A + (size_t)(m0 + row) * lda + k0 + cg * 8);
            }
#pragma unroll
            for (int i = 0; i < 2; i++) {
                int q = tid + i * 512, row = q >> 3, cg = q & 7;
                CP16(bb + SWZ128(q * 16), B + (size_t)(n0 + row) * ldb + k0 + cg * 8);
            }
            asm volatile("cp.async.commit_group;" ::: "memory");
        }
        int rem = NC - 1 - c;
        if (rem >= 2)      asm volatile("cp.async.wait_group 2;" ::: "memory");
        else if (rem == 1) asm volatile("cp.async.wait_group 1;" ::: "memory");
        else               asm volatile("cp.async.wait_group 0;" ::: "memory");
        __syncthreads();

        uint32_t ab = sb + buf * GA_BYTES;
        uint32_t bb = sb + 3 * GA_BYTES + buf * GB_BYTES;
#pragma unroll
        for (int s = 0; s < 4; s++) {
            uint32_t af[4][4];
#pragma unroll
            for (int mt = 0; mt < 4; mt++) {
                int row = wm0 + mt * 16 + rA;
                LDSM4(af[mt][0], af[mt][1], af[mt][2], af[mt][3],
                      ab + SWZ128(row * 128 + (2 * s + cA) * 16));
            }
            uint32_t bfr[8];
#pragma unroll
            for (int pr = 0; pr < 2; pr++) {
                int row = wn0 + pr * 16 + rB;
                LDSM4(bfr[4 * pr], bfr[4 * pr + 1], bfr[4 * pr + 2], bfr[4 * pr + 3],
                      bb + SWZ128(row * 128 + (2 * s + cB) * 16));
            }
#pragma unroll
            for (int mt = 0; mt < 4; mt++) {
#pragma unroll
                for (int nt = 0; nt < 4; nt++)
                    mma_f16(acc[mt][nt], af[mt], bfr[2 * nt], bfr[2 * nt + 1]);
            }
        }
    }

    int g = lid >> 2, tc = lid & 3;
#pragma unroll
    for (int mt = 0; mt < 4; mt++) {
        int row = m0 + wm0 + mt * 16 + g;
#pragma unroll
        for (int nt = 0; nt < 4; nt++) {
            int col = n0 + wn0 + nt * 8 + tc * 2;
            float v00 = acc[mt][nt][0], v01 = acc[mt][nt][1];
            float v10 = acc[mt][nt][2], v11 = acc[mt][nt][3];
            float2 bv = *(const float2*)(bias + col);
            v00 += bv.x; v01 += bv.y; v10 += bv.x; v11 += bv.y;
            if (MODE == 1) {
                v00 = fmaxf(v00, 0.f); v01 = fmaxf(v01, 0.f);
                v10 = fmaxf(v10, 0.f); v11 = fmaxf(v11, 0.f);
            }
            if (WH) {
                __half* C = (__half*)Cv;
                *(uint32_t*)(C + (size_t)row * ldc + col) = packh2(v00, v01);
                *(uint32_t*)(C + (size_t)(row + 8) * ldc + col) = packh2(v10, v11);
            } else {
                float* C = (float*)Cv;
                *(float2*)(C + (size_t)row * ldc + col) = make_float2(v00, v01);
                *(float2*)(C + (size_t)(row + 8) * ldc + col) = make_float2(v10, v11);
            }
        }
    }
}

// ---------------- fused prep (QKV-path only): round_copy | pack_bias | pack_wT ----------------
__global__ void prep_all(const float* __restrict__ x,
                         const float* __restrict__ Wq, const float* __restrict__ Wk,
                         const float* __restrict__ Wv,
                         const float* __restrict__ bq, const float* __restrict__ bk,
                         const float* __restrict__ bv) {
    __shared__ float t[32][33];
    int bid = blockIdx.x;
    int tid = threadIdx.x;
    int tx = tid & 31, ty = tid >> 5;

    if (bid < 4096) {
        int i = bid * 256 + tid;
        float4 v = ((const float4*)x)[i];
        uint32_t* o = (uint32_t*)g_xr;
        o[2 * i]     = packh2(v.x, v.y);
        o[2 * i + 1] = packh2(v.z, v.w);
    } else if (bid < 4108) {
        int i = (bid - 4096) * 256 + tid;
        if (i < 3 * DD) {
            int which = i / DD, c = i % DD;
            const float* b = (which == 0) ? bq : (which == 1) ? bk : bv;
            g_bpack[i] = b[c];
        }
    } else {
        int z = bid - 4108;
        int bx = z & 31;
        int by = (z >> 5) & 1;
        int bz = z >> 6;
        int which = bz / HH, h = bz % HH;
        const float* W = (which == 0) ? Wq : (which == 1) ? Wk : Wv;
        int d0 = bx * 32, e0 = by * 32;
#pragma unroll
        for (int i = 0; i < 32; i += 8)
            t[ty + i][tx] = W[(size_t)h * (DD * 64) + (size_t)(d0 + ty + i) * 64 + e0 + tx];
        __syncthreads();
#pragma unroll
        for (int i = 0; i < 32; i += 8)
            g_WpackT[(size_t)(which * DD + h * 64 + e0 + ty + i) * DD + d0 + tx] =
                __float2half_rn(t[tx][ty + i]);
    }
}

// ---------------- add_ln (R12 block-per-row) fused with W1/W2 transposes ----------------
// blocks [0, 4096): LN rows; [4096, 8192): W1 transpose; [8192, 12288): W2 transpose
__global__ void add_ln_prep(const float* __restrict__ xres, const float* __restrict__ a,
                            const float* __restrict__ alpha, const float* __restrict__ beta,
                            float* __restrict__ out, __half* __restrict__ outr,
                            const float* __restrict__ W1, const float* __restrict__ W2) {
    __shared__ float shm[32][33];
    int bid = blockIdx.x;
    int tid = threadIdx.x;

    if (bid < 4096) {
        int row = bid;
        int wid = tid >> 5, lid = tid & 31;
        float4 v = ((const float4*)(a + (size_t)row * DD))[tid];
        float s  = (v.x + v.y) + (v.z + v.w);
        float sq = v.x * v.x + v.y * v.y + v.z * v.z + v.w * v.w;
#pragma unroll
        for (int o = 16; o > 0; o >>= 1) {
            s  += __shfl_xor_sync(0xffffffff, s, o);
            sq += __shfl_xor_sync(0xffffffff, sq, o);
        }
        float* red = &shm[0][0];
        if (lid == 0) { red[wid] = s; red[wid + 8] = sq; }
        __syncthreads();
        if (tid < 8) {
            float ws = red[tid], wq = red[tid + 8];
#pragma unroll
            for (int o = 4; o > 0; o >>= 1) {
                ws += __shfl_xor_sync(0xff, ws, o);
                wq += __shfl_xor_sync(0xff, wq, o);
            }
            if (tid == 0) { red[0] = ws; red[1] = wq; }
        }
        __syncthreads();
        float S = red[0], SQ = red[1];
        float mean = S * (1.f / DD);
        float var = (SQ - (float)DD * mean * mean) * (1.f / (DD - 1));
        float inv = 1.f / (sqrtf(fmaxf(var, 0.f)) + 1e-6f);

        float4 xr4 = ((const float4*)(xres + (size_t)row * DD))[tid];
        float4 al4 = ((const float4*)alpha)[tid];
        float4 be4 = ((const float4*)beta)[tid];
        float4 o4;
        o4.x = xr4.x + al4.x * (v.x - mean) * inv + be4.x;
        o4.y = xr4.y + al4.y * (v.y - mean) * inv + be4.y;
        o4.z = xr4.z + al4.z * (v.z - mean) * inv + be4.z;
        o4.w = xr4.w + al4.w * (v.w - mean) * inv + be4.w;
        ((float4*)(out + (size_t)row * DD))[tid] = o4;
        uint32_t* oh = (uint32_t*)(outr + (size_t)row * DD);
        oh[2 * tid]     = packh2(o4.x, o4.y);
        oh[2 * tid + 1] = packh2(o4.z, o4.w);
    } else if (bid < 8192) {
        // transpose W1 [DD, DFF] -> W1T [DFF, DD] fp16
        int z = bid - 4096;
        int tx = tid & 31, ty = tid >> 5;
        int bx = z & 127;
        int by = z >> 7;
        int c0 = bx * 32, r0 = by * 32;
#pragma unroll
        for (int i = 0; i < 32; i += 8)
            shm[ty + i][tx] = W1[(size_t)(r0 + ty + i) * DFF + c0 + tx];
        __syncthreads();
#pragma unroll
        for (int i = 0; i < 32; i += 8)
            g_W1T[(size_t)(c0 + ty + i) * DD + r0 + tx] = __float2half_rn(shm[tx][ty + i]);
    } else {
        // transpose W2 [DFF, DD] -> W2T [DD, DFF] fp16
        int z = bid - 8192;
        int tx = tid & 31, ty = tid >> 5;
        int bx = z & 31;
        int by = z >> 5;
        int c0 = bx * 32, r0 = by * 32;
#pragma unroll
        for (int i = 0; i < 32; i += 8)
            shm[ty + i][tx] = W2[(size_t)(r0 + ty + i) * DD + c0 + tx];
        __syncthreads();
#pragma unroll
        for (int i = 0; i < 32; i += 8)
            g_W2T[(size_t)(c0 + ty + i) * DFF + r0 + tx] = __float2half_rn(shm[tx][ty + i]);
    }
}

// ---------------- plain add_ln (R12 block-per-row), final LN ----------------
__global__ void add_ln_final(const float* __restrict__ xres, const float* __restrict__ a,
                             const float* __restrict__ alpha, const float* __restrict__ beta,
                             float* __restrict__ out) {
    int row = blockIdx.x;
    int tid = threadIdx.x;
    int wid = tid >> 5, lid = tid & 31;

    float4 v = ((const float4*)(a + (size_t)row * DD))[tid];
    float s  = (v.x + v.y) + (v.z + v.w);
    float sq = v.x * v.x + v.y * v.y + v.z * v.z + v.w * v.w;
#pragma unroll
    for (int o = 16; o > 0; o >>= 1) {
        s  += __shfl_xor_sync(0xffffffff, s, o);
        sq += __shfl_xor_sync(0xffffffff, sq, o);
    }
    __shared__ float red[16];
    if (lid == 0) { red[wid] = s; red[wid + 8] = sq; }
    __syncthreads();
    if (tid < 8) {
        float ws = red[tid], wq = red[tid + 8];
#pragma unroll
        for (int o = 4; o > 0; o >>= 1) {
            ws += __shfl_xor_sync(0xff, ws, o);
            wq += __shfl_xor_sync(0xff, wq, o);
        }
        if (tid == 0) { red[0] = ws; red[1] = wq; }
    }
    __syncthreads();
    float S = red[0], SQ = red[1];
    float mean = S * (1.f / DD);
    float var = (SQ - (float)DD * mean * mean) * (1.f / (DD - 1));
    float inv = 1.f / (sqrtf(fmaxf(var, 0.f)) + 1e-6f);

    float4 xr4 = ((const float4*)(xres + (size_t)row * DD))[tid];
    float4 al4 = ((const float4*)alpha)[tid];
    float4 be4 = ((const float4*)beta)[tid];
    float4 o4;
    o4.x = xr4.x + al4.x * (v.x - mean) * inv + be4.x;
    o4.y = xr4.y + al4.y * (v.y - mean) * inv + be4.y;
    o4.z = xr4.z + al4.z * (v.z - mean) * inv + be4.z;
    o4.w = xr4.w + al4.w * (v.w - mean) * inv + be4.w;
    ((float4*)(out + (size_t)row * DD))[tid] = o4;
}

// ---------------- launch ----------------
extern "C" void kernel_launch(void* const* d_in, const int* in_sizes, int n_in,
                              void* d_out, int out_size) {
    const float* x      = (const float*)d_in[0];
    const int*   mask   = (const int*)d_in[1];
    const float* Wq     = (const float*)d_in[2];
    const float* bq     = (const float*)d_in[3];
    const float* Wk     = (const float*)d_in[4];
    const float* bk     = (const float*)d_in[5];
    const float* Wv     = (const float*)d_in[6];
    const float* bv     = (const float*)d_in[7];
    const float* W1     = (const float*)d_in[8];
    const float* b1     = (const float*)d_in[9];
    const float* W2     = (const float*)d_in[10];
    const float* b2     = (const float*)d_in[11];
    const float* alpha1 = (const float*)d_in[12];
    const float* beta1  = (const float*)d_in[13];
    const float* alpha2 = (const float*)d_in[14];
    const float* beta2  = (const float*)d_in[15];
    float* out = (float*)d_out;

    __half *xr, *WpackT, *W1T, *W2T, *QKV, *x1r, *h1;
    float *bpack, *attn, *x1, *ffn;
    cudaGetSymbolAddress((void**)&xr,     g_xr);
    cudaGetSymbolAddress((void**)&WpackT, g_WpackT);
    cudaGetSymbolAddress((void**)&bpack,  g_bpack);
    cudaGetSymbolAddress((void**)&W1T,    g_W1T);
    cudaGetSymbolAddress((void**)&W2T,    g_W2T);
    cudaGetSymbolAddress((void**)&QKV,    g_QKV);
    cudaGetSymbolAddress((void**)&attn,   g_attn);
    cudaGetSymbolAddress((void**)&x1,     g_x1);
    cudaGetSymbolAddress((void**)&x1r,    g_x1r);
    cudaGetSymbolAddress((void**)&h1,     g_h1);
    cudaGetSymbolAddress((void**)&ffn,    g_ffn);

    cudaFuncSetAttribute(mma_gemm<0, true>,  cudaFuncAttributeMaxDynamicSharedMemorySize, G_SMEM);
    cudaFuncSetAttribute(mma_gemm<1, true>,  cudaFuncAttributeMaxDynamicSharedMemorySize, G_SMEM);
    cudaFuncSetAttribute(mma_gemm<0, false>, cudaFuncAttributeMaxDynamicSharedMemorySize, G_SMEM);
    cudaFuncSetAttribute(flash_attn, cudaFuncAttributeMaxDynamicSharedMemorySize, FA_SMEM);

    // prep for QKV path only (x round, bias pack, Wqkv pack): 4108 + 3072 blocks
    prep_all<<<7180, 256>>>(x, Wq, Wk, Wv, bq, bk, bv);

    // QKV = xr @ WpackT^T + bias  [4096, 3072] fp16 out
    mma_gemm<0, true><<<dim3(24, 16), 512, G_SMEM>>>(
        xr, DD, WpackT, DD, QKV, 3 * DD, bpack, DD);

    // fused attention: scores + mask + softmax + P@V (fp16 mma, fp32 out)
    flash_attn<<<dim3(16, 32), 256, FA_SMEM>>>(QKV, mask, attn);

    // x1 = x + LN1(attn)  (fp32 + fp16 copy), with W1/W2 transposes riding along
    add_ln_prep<<<12288, 256>>>(x, attn, alpha1, beta1, x1, x1r, W1, W2);

    // FFN1: relu(x1r @ W1 + b1) fp16 out
    mma_gemm<1, true><<<dim3(32, 16), 512, G_SMEM>>>(
        x1r, DD, W1T, DD, h1, DFF, b1, DD);

    // FFN2: h1 @ W2 + b2  fp32 out
    mma_gemm<0, false><<<dim3(8, 16), 512, G_SMEM>>>(
        h1, DFF, W2T, DFF, ffn, DD, b2, DFF);

    // out = x1 + LN2(ffn)
    add_ln_final<<<MTOK, 256>>>(x1, ffn, alpha2, beta2, out);
}

// round 15
// speedup vs baseline: 1.0175x; 1.0133x over previous
#include <cuda_runtime.h>
#include <cuda_fp16.h>
#include <math.h>
#include <stdint.h>

#define BB 2
#define SS 2048
#define DD 1024
#define HH 16
#define DFF 4096
#define MTOK 4096

// ---------------- scratch (no allocations allowed) ----------------
__device__ __half g_xr[(size_t)MTOK * DD];           // fp16 x
__device__ __half g_WpackT[(size_t)3 * DD * DD];     // [3D, D] K-major packed qkv weights
__device__ float  g_bpack[3 * DD];
__device__ __half g_W1T[(size_t)DFF * DD];           // [4D, D]
__device__ __half g_W2T[(size_t)DD * DFF];           // [D, 4D]
__device__ __half g_QKV[(size_t)MTOK * 3 * DD];      // [tok, 3D] fp16
__device__ float  g_attn[(size_t)MTOK * DD];
__device__ float  g_x1[(size_t)MTOK * DD];           // exact
__device__ __half g_x1r[(size_t)MTOK * DD];          // fp16
__device__ __half g_h1[(size_t)MTOK * DFF];          // fp16
__device__ float  g_ffn[(size_t)MTOK * DD];

// ---------------- helpers ----------------
__device__ __forceinline__ uint32_t smem_u32(const void* p) {
    uint32_t a;
    asm("{ .reg .u64 t; cvta.to.shared.u64 t, %1; cvt.u32.u64 %0, t; }" : "=r"(a) : "l"(p));
    return a;
}
__device__ __forceinline__ uint32_t packh2(float lo, float hi) {
    uint32_t u;
    asm("cvt.rn.f16x2.f32 %0, %1, %2;" : "=r"(u) : "f"(hi), "f"(lo));
    return u;
}
#define SWZ128(o) ((o) ^ (((o) >> 3) & 0x70))
#define CP16(dst, src) asm volatile("cp.async.cg.shared.global [%0], [%1], 16;" :: "r"(dst), "l"(src))
#define LDSM4(r0, r1, r2, r3, a) \
    asm volatile("ldmatrix.sync.aligned.m8n8.x4.shared.b16 {%0,%1,%2,%3}, [%4];" \
                 : "=r"(r0), "=r"(r1), "=r"(r2), "=r"(r3) : "r"(a))
#define LDSM4T(r0, r1, r2, r3, a) \
    asm volatile("ldmatrix.sync.aligned.m8n8.x4.trans.shared.b16 {%0,%1,%2,%3}, [%4];" \
                 : "=r"(r0), "=r"(r1), "=r"(r2), "=r"(r3) : "r"(a))

__device__ __forceinline__ void mma_f16(float* d, const uint32_t* a, uint32_t b0, uint32_t b1) {
    asm volatile(
        "mma.sync.aligned.m16n8k16.row.col.f32.f16.f16.f32 "
        "{%0,%1,%2,%3}, {%4,%5,%6,%7}, {%8,%9}, {%0,%1,%2,%3};"
        : "+f"(d[0]), "+f"(d[1]), "+f"(d[2]), "+f"(d[3])
        : "r"(a[0]), "r"(a[1]), "r"(a[2]), "r"(a[3]), "r"(b0), "r"(b1));
}

// ================= FLASH ATTENTION (fp16, 128 q-rows/CTA) — R8 frozen =================
#define FK_BYTES 16384
#define FV_BYTES 16384
#define OFF_Q 0
#define OFF_K 16384
#define OFF_V 49152
#define OFF_M 81920
#define FA_SMEM 90112

__global__ void __launch_bounds__(256, 1)
flash_attn(const __half* __restrict__ QKV, const int* __restrict__ mask,
           float* __restrict__ out) {
    extern __shared__ char smem[];
    const uint32_t sb = smem_u32(smem);
    int tid = threadIdx.x, wid = tid >> 5, lid = tid & 31;
    int g = lid >> 2, tc = lid & 3;
    int qt = blockIdx.x, bh = blockIdx.y;
    int b = bh >> 4, h = bh & 15;
    int q0 = qt * 128;
    int wq0 = wid * 16;
    const __half* base = QKV + (size_t)b * SS * 3072 + h * 64;

    int rA = (lid & 7) + ((lid >> 3) & 1) * 8;
    int cA = lid >> 4;
    int rB = (lid & 7) + ((lid >> 4) & 1) * 8;
    int cB = (lid >> 3) & 1;

#pragma unroll
    for (int i = 0; i < 4; i++) {
        int q = tid + i * 256, r = q >> 3, c = q & 7;
        CP16(sb + OFF_Q + SWZ128(q * 16), base + (size_t)(q0 + r) * 3072 + c * 8);
    }
#pragma unroll
    for (int i = 0; i < 4; i++) {
        int q = tid + i * 256, r = q >> 3, c = q & 7;
        CP16(sb + OFF_K + SWZ128(q * 16), base + (size_t)r * 3072 + 1024 + c * 8);
    }
#pragma unroll
    for (int i = 0; i < 4; i++) {
        int q = tid + i * 256, r = q >> 3, c = q & 7;
        CP16(sb + OFF_V + SWZ128(q * 16), base + (size_t)r * 3072 + 2048 + c * 8);
    }
    asm volatile("cp.async.commit_group;" ::: "memory");
    int* msmem = (int*)(smem + OFF_M);
#pragma unroll
    for (int i = 0; i < 8; i++) {
        int idx = tid + i * 256;
        msmem[idx] = mask[b * SS + idx];
    }
    asm volatile("cp.async.wait_group 0;" ::: "memory");
    __syncthreads();

    uint32_t af[4][4];
#pragma unroll
    for (int s = 0; s < 4; s++) {
        uint32_t addr = sb + OFF_Q + SWZ128((wq0 + rA) * 128 + (2 * s + cA) * 16);
        LDSM4(af[s][0], af[s][1], af[s][2], af[s][3], addr);
    }

    float oacc[8][4];
#pragma unroll
    for (int i = 0; i < 8; i++)
#pragma unroll
        for (int j = 0; j < 4; j++) oacc[i][j] = 0.f;
    float l0 = 0.f, l1 = 0.f, m0 = -INFINITY, m1 = -INFINITY;

    for (int it = 0; it < 16; it++) {
        int buf = it & 1;
        if (it + 1 < 16) {
            int kv1 = (it + 1) * 128, nb = buf ^ 1;
#pragma unroll
            for (int i = 0; i < 4; i++) {
                int q = tid + i * 256, r = q >> 3, c = q & 7;
                CP16(sb + OFF_K + nb * FK_BYTES + SWZ128(q * 16),
                     base + (size_t)(kv1 + r) * 3072 + 1024 + c * 8);
            }
#pragma unroll
            for (int i = 0; i < 4; i++) {
                int q = tid + i * 256, r = q >> 3, c = q & 7;
                CP16(sb + OFF_V + nb * FV_BYTES + SWZ128(q * 16),
                     base + (size_t)(kv1 + r) * 3072 + 2048 + c * 8);
            }
            asm volatile("cp.async.commit_group;" ::: "memory");
        }
        if (it > 0) {
            if (it + 1 < 16) asm volatile("cp.async.wait_group 1;" ::: "memory");
            else             asm volatile("cp.async.wait_group 0;" ::: "memory");
            __syncthreads();
        }

        int kv0 = it * 128;
        uint32_t kb = sb + OFF_K + buf * FK_BYTES;
        uint32_t vb = sb + OFF_V + buf * FV_BYTES;

        float sacc[16][4];
#pragma unroll
        for (int i = 0; i < 16; i++)
#pragma unroll
            for (int j = 0; j < 4; j++) sacc[i][j] = 0.f;
#pragma unroll
        for (int np = 0; np < 8; np++) {
            int nrow = 16 * np + rB;
#pragma unroll
            for (int s = 0; s < 4; s++) {
                uint32_t bq[4];
                LDSM4(bq[0], bq[1], bq[2], bq[3],
                      kb + SWZ128(nrow * 128 + (2 * s + cB) * 16));
                mma_f16(sacc[2 * np],     af[s], bq[0], bq[1]);
                mma_f16(sacc[2 * np + 1], af[s], bq[2], bq[3]);
            }
        }

        float mt0 = -INFINITY, mt1 = -INFINITY;
#pragma unroll
        for (int nt = 0; nt < 16; nt++) {
            int c0 = kv0 + 8 * nt + 2 * tc;
            int mk0 = msmem[c0], mk1 = msmem[c0 + 1];
            float s0 = sacc[nt][0] * 0.125f, s1 = sacc[nt][1] * 0.125f;
            float s2 = sacc[nt][2] * 0.125f, s3 = sacc[nt][3] * 0.125f;
            if (mk0 == 0) { s0 = -INFINITY; s2 = -INFINITY; }
            if (mk1 == 0) { s1 = -INFINITY; s3 = -INFINITY; }
            sacc[nt][0] = s0; sacc[nt][1] = s1; sacc[nt][2] = s2; sacc[nt][3] = s3;
            mt0 = fmaxf(mt0, fmaxf(s0, s1));
            mt1 = fmaxf(mt1, fmaxf(s2, s3));
        }
        mt0 = fmaxf(mt0, __shfl_xor_sync(0xffffffff, mt0, 1));
        mt0 = fmaxf(mt0, __shfl_xor_sync(0xffffffff, mt0, 2));
        mt1 = fmaxf(mt1, __shfl_xor_sync(0xffffffff, mt1, 1));
        mt1 = fmaxf(mt1, __shfl_xor_sync(0xffffffff, mt1, 2));
        float mn0 = fmaxf(m0, mt0), mn1 = fmaxf(m1, mt1);
        float al0 = __expf(m0 - mn0), al1 = __expf(m1 - mn1);
        l0 *= al0; l1 *= al1;
#pragma unroll
        for (int i = 0; i < 8; i++) {
            oacc[i][0] *= al0; oacc[i][1] *= al0;
            oacc[i][2] *= al1; oacc[i][3] *= al1;
        }
#pragma unroll
        for (int nt = 0; nt < 16; nt++) {
            float p0 = __expf(sacc[nt][0] - mn0);
            float p1 = __expf(sacc[nt][1] - mn0);
            float p2 = __expf(sacc[nt][2] - mn1);
            float p3 = __expf(sacc[nt][3] - mn1);
            l0 += p0 + p1; l1 += p2 + p3;
            sacc[nt][0] = p0; sacc[nt][1] = p1;
            sacc[nt][2] = p2; sacc[nt][3] = p3;
        }
        m0 = mn0; m1 = mn1;

#pragma unroll
        for (int kc = 0; kc < 8; kc++) {
            uint32_t afr[4];
            afr[0] = packh2(sacc[2 * kc][0],     sacc[2 * kc][1]);
            afr[1] = packh2(sacc[2 * kc][2],     sacc[2 * kc][3]);
            afr[2] = packh2(sacc[2 * kc + 1][0], sacc[2 * kc + 1][1]);
            afr[3] = packh2(sacc[2 * kc + 1][2], sacc[2 * kc + 1][3]);
            int vrow = 16 * kc + rA;
#pragma unroll
            for (int np = 0; np < 4; np++) {
                uint32_t bv[4];
                LDSM4T(bv[0], bv[1], bv[2], bv[3],
                       vb + SWZ128(vrow * 128 + np * 32 + cA * 16));
                mma_f16(oacc[2 * np],     afr, bv[0], bv[1]);
                mma_f16(oacc[2 * np + 1], afr, bv[2], bv[3]);
            }
        }
        __syncthreads();
    }

    l0 += __shfl_xor_sync(0xffffffff, l0, 1);
    l0 += __shfl_xor_sync(0xffffffff, l0, 2);
    l1 += __shfl_xor_sync(0xffffffff, l1, 1);
    l1 += __shfl_xor_sync(0xffffffff, l1, 2);

    float il0 = 1.f / l0, il1 = 1.f / l1;
    int r0 = q0 + wq0 + g, r1 = r0 + 8;
    float* o0 = out + (size_t)(b * SS + r0) * DD + h * 64 + 2 * tc;
    float* o1 = out + (size_t)(b * SS + r1) * DD + h * 64 + 2 * tc;
#pragma unroll
    for (int nt = 0; nt < 8; nt++) {
        *(float2*)(o0 + nt * 8) = make_float2(oacc[nt][0] * il0, oacc[nt][1] * il0);
        *(float2*)(o1 + nt * 8) = make_float2(oacc[nt][2] * il1, oacc[nt][3] * il1);
    }
}

// ---------------- fp16 mma GEMM: 256x128 tile, BK=64, 512 threads, 4-stage ----------------
// single barrier per K-chunk: prefetch slot (c+3)%4 never collides with read slot (c-1)%4
#define GA_BYTES 32768
#define GB_BYTES 16384
#define G_SMEM (4 * (GA_BYTES + GB_BYTES))

template <int MODE, bool WH>
__global__ void __launch_bounds__(512)
mma_gemm(const __half* __restrict__ A, int lda,
         const __half* __restrict__ B, int ldb,
         void* __restrict__ Cv, int ldc,
         const float* __restrict__ bias, int K) {
    extern __shared__ char smem[];
    const uint32_t sb = smem_u32(smem);
    int tid = threadIdx.x, wid = tid >> 5, lid = tid & 31;
    int m0 = blockIdx.y * 256, n0 = blockIdx.x * 128;
    int wm0 = (wid >> 2) * 64, wn0 = (wid & 3) * 32;

    int rA = (lid & 7) + ((lid >> 3) & 1) * 8;
    int cA = lid >> 4;
    int rB = (lid & 7) + ((lid >> 4) & 1) * 8;
    int cB = (lid >> 3) & 1;

    float acc[4][4][4];
#pragma unroll
    for (int i = 0; i < 4; i++)
#pragma unroll
        for (int j = 0; j < 4; j++)
#pragma unroll
            for (int r = 0; r < 4; r++) acc[i][j][r] = 0.f;

    const int NC = K >> 6;

    // prologue: stage chunks 0, 1, 2
#pragma unroll
    for (int pc = 0; pc < 3; pc++) {
        int k0 = pc << 6;
        uint32_t ab = sb + pc * GA_BYTES;
        uint32_t bb = sb + 4 * GA_BYTES + pc * GB_BYTES;
#pragma unroll
        for (int i = 0; i < 4; i++) {
            int q = tid + i * 512, row = q >> 3, cg = q & 7;
            CP16(ab + SWZ128(q * 16), A + (size_t)(m0 + row) * lda + k0 + cg * 8);
        }
#pragma unroll
        for (int i = 0; i < 2; i++) {
            int q = tid + i * 512, row = q >> 3, cg = q & 7;
            CP16(bb + SWZ128(q * 16), B + (size_t)(n0 + row) * ldb + k0 + cg * 8);
        }
        asm volatile("cp.async.commit_group;" ::: "memory");
    }

    for (int c = 0; c < NC; c++) {
        int slot = c & 3;
        int rem = NC - 1 - c;
        if (rem >= 2)      asm volatile("cp.async.wait_group 2;" ::: "memory");
        else if (rem == 1) asm volatile("cp.async.wait_group 1;" ::: "memory");
        else               asm volatile("cp.async.wait_group 0;" ::: "memory");
        __syncthreads();

        // prefetch chunk c+3 into slot (c+3)&3 == (c-1)&3 (reads of it finished pre-barrier)
        if (c + 3 < NC) {
            int k0 = (c + 3) << 6;
            int lb = (c + 3) & 3;
            uint32_t ab = sb + lb * GA_BYTES;
            uint32_t bb = sb + 4 * GA_BYTES + lb * GB_BYTES;
#pragma unroll
            for (int i = 0; i < 4; i++) {
                int q = tid + i * 512, row = q >> 3, cg = q & 7;
                CP16(ab + SWZ128(q * 16), A + (size_t)(m0 + row) * lda + k0 + cg * 8);
            }
#pragma unroll
            for (int i = 0; i < 2; i++) {
                int q = tid + i * 512, row = q >> 3, cg = q & 7;
                CP16(bb + SWZ128(q * 16), B + (size_t)(n0 + row) * ldb + k0 + cg * 8);
            }
            asm volatile("cp.async.commit_group;" ::: "memory");
        }

        uint32_t ab = sb + slot * GA_BYTES;
        uint32_t bb = sb + 4 * GA_BYTES + slot * GB_BYTES;
#pragma unroll
        for (int s = 0; s < 4; s++) {
            uint32_t af[4][4];
#pragma unroll
            for (int mt = 0; mt < 4; mt++) {
                int row = wm0 + mt * 16 + rA;
                LDSM4(af[mt][0], af[mt][1], af[mt][2], af[mt][3],
                      ab + SWZ128(row * 128 + (2 * s + cA) * 16));
            }
            uint32_t bfr[8];
#pragma unroll
            for (int pr = 0; pr < 2; pr++) {
                int row = wn0 + pr * 16 + rB;
                LDSM4(bfr[4 * pr], bfr[4 * pr + 1], bfr[4 * pr + 2], bfr[4 * pr + 3],
                      bb + SWZ128(row * 128 + (2 * s + cB) * 16));
            }
#pragma unroll
            for (int mt = 0; mt < 4; mt++) {
#pragma unroll
                for (int nt = 0; nt < 4; nt++)
                    mma_f16(acc[mt][nt], af[mt], bfr[2 * nt], bfr[2 * nt + 1]);
            }
        }
    }

    int g = lid >> 2, tc = lid & 3;
#pragma unroll
    for (int mt = 0; mt < 4; mt++) {
        int row = m0 + wm0 + mt * 16 + g;
#pragma unroll
        for (int nt = 0; nt < 4; nt++) {
            int col = n0 + wn0 + nt * 8 + tc * 2;
            float v00 = acc[mt][nt][0], v01 = acc[mt][nt][1];
            float v10 = acc[mt][nt][2], v11 = acc[mt][nt][3];
            float2 bv = *(const float2*)(bias + col);
            v00 += bv.x; v01 += bv.y; v10 += bv.x; v11 += bv.y;
            if (MODE == 1) {
                v00 = fmaxf(v00, 0.f); v01 = fmaxf(v01, 0.f);
                v10 = fmaxf(v10, 0.f); v11 = fmaxf(v11, 0.f);
            }
            if (WH) {
                __half* C = (__half*)Cv;
                *(uint32_t*)(C + (size_t)row * ldc + col) = packh2(v00, v01);
                *(uint32_t*)(C + (size_t)(row + 8) * ldc + col) = packh2(v10, v11);
            } else {
                float* C = (float*)Cv;
                *(float2*)(C + (size_t)row * ldc + col) = make_float2(v00, v01);
                *(float2*)(C + (size_t)(row + 8) * ldc + col) = make_float2(v10, v11);
            }
        }
    }
}

// ---------------- fused prep (QKV-path only): round_copy | pack_bias | pack_wT ----------------
__global__ void prep_all(const float* __restrict__ x,
                         const float* __restrict__ Wq, const float* __restrict__ Wk,
                         const float* __restrict__ Wv,
                         const float* __restrict__ bq, const float* __restrict__ bk,
                         const float* __restrict__ bv) {
    __shared__ float t[32][33];
    int bid = blockIdx.x;
    int tid = threadIdx.x;
    int tx = tid & 31, ty = tid >> 5;

    if (bid < 4096) {
        int i = bid * 256 + tid;
        float4 v = ((const float4*)x)[i];
        uint32_t* o = (uint32_t*)g_xr;
        o[2 * i]     = packh2(v.x, v.y);
        o[2 * i + 1] = packh2(v.z, v.w);
    } else if (bid < 4108) {
        int i = (bid - 4096) * 256 + tid;
        if (i < 3 * DD) {
            int which = i / DD, c = i % DD;
            const float* b = (which == 0) ? bq : (which == 1) ? bk : bv;
            g_bpack[i] = b[c];
        }
    } else {
        int z = bid - 4108;
        int bx = z & 31;
        int by = (z >> 5) & 1;
        int bz = z >> 6;
        int which = bz / HH, h = bz % HH;
        const float* W = (which == 0) ? Wq : (which == 1) ? Wk : Wv;
        int d0 = bx * 32, e0 = by * 32;
#pragma unroll
        for (int i = 0; i < 32; i += 8)
            t[ty + i][tx] = W[(size_t)h * (DD * 64) + (size_t)(d0 + ty + i) * 64 + e0 + tx];
        __syncthreads();
#pragma unroll
        for (int i = 0; i < 32; i += 8)
            g_WpackT[(size_t)(which * DD + h * 64 + e0 + ty + i) * DD + d0 + tx] =
                __float2half_rn(t[tx][ty + i]);
    }
}

// ---------------- add_ln (block-per-row) fused with W1/W2 transposes ----------------
__global__ void add_ln_prep(const float* __restrict__ xres, const float* __restrict__ a,
                            const float* __restrict__ alpha, const float* __restrict__ beta,
                            float* __restrict__ out, __half* __restrict__ outr,
                            const float* __restrict__ W1, const float* __restrict__ W2) {
    __shared__ float shm[32][33];
    int bid = blockIdx.x;
    int tid = threadIdx.x;

    if (bid < 4096) {
        int row = bid;
        int wid = tid >> 5, lid = tid & 31;
        float4 v = ((const float4*)(a + (size_t)row * DD))[tid];
        float s  = (v.x + v.y) + (v.z + v.w);
        float sq = v.x * v.x + v.y * v.y + v.z * v.z + v.w * v.w;
#pragma unroll
        for (int o = 16; o > 0; o >>= 1) {
            s  += __shfl_xor_sync(0xffffffff, s, o);
            sq += __shfl_xor_sync(0xffffffff, sq, o);
        }
        float* red = &shm[0][0];
        if (lid == 0) { red[wid] = s; red[wid + 8] = sq; }
        __syncthreads();
        if (tid < 8) {
            float ws = red[tid], wq = red[tid + 8];
#pragma unroll
            for (int o = 4; o > 0; o >>= 1) {
                ws += __shfl_xor_sync(0xff, ws, o);
                wq += __shfl_xor_sync(0xff, wq, o);
            }
            if (tid == 0) { red[0] = ws; red[1] = wq; }
        }
        __syncthreads();
        float S = red[0], SQ = red[1];
        float mean = S * (1.f / DD);
        float var = (SQ - (float)DD * mean * mean) * (1.f / (DD - 1));
        float inv = 1.f / (sqrtf(fmaxf(var, 0.f)) + 1e-6f);

        float4 xr4 = ((const float4*)(xres + (size_t)row * DD))[tid];
        float4 al4 = ((const float4*)alpha)[tid];
        float4 be4 = ((const float4*)beta)[tid];
        float4 o4;
        o4.x = xr4.x + al4.x * (v.x - mean) * inv + be4.x;
        o4.y = xr4.y + al4.y * (v.y - mean) * inv + be4.y;
        o4.z = xr4.z + al4.z * (v.z - mean) * inv + be4.z;
        o4.w = xr4.w + al4.w * (v.w - mean) * inv + be4.w;
        ((float4*)(out + (size_t)row * DD))[tid] = o4;
        uint32_t* oh = (uint32_t*)(outr + (size_t)row * DD);
        oh[2 * tid]     = packh2(o4.x, o4.y);
        oh[2 * tid + 1] = packh2(o4.z, o4.w);
    } else if (bid < 8192) {
        int z = bid - 4096;
        int tx = tid & 31, ty = tid >> 5;
        int bx = z & 127;
        int by = z >> 7;
        int c0 = bx * 32, r0 = by * 32;
#pragma unroll
        for (int i = 0; i < 32; i += 8)
            shm[ty + i][tx] = W1[(size_t)(r0 + ty + i) * DFF + c0 + tx];
        __syncthreads();
#pragma unroll
        for (int i = 0; i < 32; i += 8)
            g_W1T[(size_t)(c0 + ty + i) * DD + r0 + tx] = __float2half_rn(shm[tx][ty + i]);
    } else {
        int z = bid - 8192;
        int tx = tid & 31, ty = tid >> 5;
        int bx = z & 31;
        int by = z >> 5;
        int c0 = bx * 32, r0 = by * 32;
#pragma unroll
        for (int i = 0; i < 32; i += 8)
            shm[ty + i][tx] = W2[(size_t)(r0 + ty + i) * DD + c0 + tx];
        __syncthreads();
#pragma unroll
        for (int i = 0; i < 32; i += 8)
            g_W2T[(size_t)(c0 + ty + i) * DFF + r0 + tx] = __float2half_rn(shm[tx][ty + i]);
    }
}

// ---------------- plain add_ln (block-per-row), final LN ----------------
__global__ void add_ln_final(const float* __restrict__ xres, const float* __restrict__ a,
                             const float* __restrict__ alpha, const float* __restrict__ beta,
                             float* __restrict__ out) {
    int row = blockIdx.x;
    int tid = threadIdx.x;
    int wid = tid >> 5, lid = tid & 31;

    float4 v = ((const float4*)(a + (size_t)row * DD))[tid];
    float s  = (v.x + v.y) + (v.z + v.w);
    float sq = v.x * v.x + v.y * v.y + v.z * v.z + v.w * v.w;
#pragma unroll
    for (int o = 16; o > 0; o >>= 1) {
        s  += __shfl_xor_sync(0xffffffff, s, o);
        sq += __shfl_xor_sync(0xffffffff, sq, o);
    }
    __shared__ float red[16];
    if (lid == 0) { red[wid] = s; red[wid + 8] = sq; }
    __syncthreads();
    if (tid < 8) {
        float ws = red[tid], wq = red[tid + 8];
#pragma unroll
        for (int o = 4; o > 0; o >>= 1) {
            ws += __shfl_xor_sync(0xff, ws, o);
            wq += __shfl_xor_sync(0xff, wq, o);
        }
        if (tid == 0) { red[0] = ws; red[1] = wq; }
    }
    __syncthreads();
    float S = red[0], SQ = red[1];
    float mean = S * (1.f / DD);
    float var = (SQ - (float)DD * mean * mean) * (1.f / (DD - 1));
    float inv = 1.f / (sqrtf(fmaxf(var, 0.f)) + 1e-6f);

    float4 xr4 = ((const float4*)(xres + (size_t)row * DD))[tid];
    float4 al4 = ((const float4*)alpha)[tid];
    float4 be4 = ((const float4*)beta)[tid];
    float4 o4;
    o4.x = xr4.x + al4.x * (v.x - mean) * inv + be4.x;
    o4.y = xr4.y + al4.y * (v.y - mean) * inv + be4.y;
    o4.z = xr4.z + al4.z * (v.z - mean) * inv + be4.z;
    o4.w = xr4.w + al4.w * (v.w - mean) * inv + be4.w;
    ((float4*)(out + (size_t)row * DD))[tid] = o4;
}

// ---------------- launch ----------------
extern "C" void kernel_launch(void* const* d_in, const int* in_sizes, int n_in,
                              void* d_out, int out_size) {
    const float* x      = (const float*)d_in[0];
    const int*   mask   = (const int*)d_in[1];
    const float* Wq     = (const float*)d_in[2];
    const float* bq     = (const float*)d_in[3];
    const float* Wk     = (const float*)d_in[4];
    const float* bk     = (const float*)d_in[5];
    const float* Wv     = (const float*)d_in[6];
    const float* bv     = (const float*)d_in[7];
    const float* W1     = (const float*)d_in[8];
    const float* b1     = (const float*)d_in[9];
    const float* W2     = (const float*)d_in[10];
    const float* b2     = (const float*)d_in[11];
    const float* alpha1 = (const float*)d_in[12];
    const float* beta1  = (const float*)d_in[13];
    const float* alpha2 = (const float*)d_in[14];
    const float* beta2  = (const float*)d_in[15];
    float* out = (float*)d_out;

    __half *xr, *WpackT, *W1T, *W2T, *QKV, *x1r, *h1;
    float *bpack, *attn, *x1, *ffn;
    cudaGetSymbolAddress((void**)&xr,     g_xr);
    cudaGetSymbolAddress((void**)&WpackT, g_WpackT);
    cudaGetSymbolAddress((void**)&bpack,  g_bpack);
    cudaGetSymbolAddress((void**)&W1T,    g_W1T);
    cudaGetSymbolAddress((void**)&W2T,    g_W2T);
    cudaGetSymbolAddress((void**)&QKV,    g_QKV);
    cudaGetSymbolAddress((void**)&attn,   g_attn);
    cudaGetSymbolAddress((void**)&x1,     g_x1);
    cudaGetSymbolAddress((void**)&x1r,    g_x1r);
    cudaGetSymbolAddress((void**)&h1,     g_h1);
    cudaGetSymbolAddress((void**)&ffn,    g_ffn);

    cudaFuncSetAttribute(mma_gemm<0, true>,  cudaFuncAttributeMaxDynamicSharedMemorySize, G_SMEM);
    cudaFuncSetAttribute(mma_gemm<1, true>,  cudaFuncAttributeMaxDynamicSharedMemorySize, G_SMEM);
    cudaFuncSetAttribute(mma_gemm<0, false>, cudaFuncAttributeMaxDynamicSharedMemorySize, G_SMEM);
    cudaFuncSetAttribute(flash_attn, cudaFuncAttributeMaxDynamicSharedMemorySize, FA_SMEM);

    // prep for QKV path only (x round, bias pack, Wqkv pack)
    prep_all<<<7180, 256>>>(x, Wq, Wk, Wv, bq, bk, bv);

    // QKV = xr @ WpackT^T + bias  [4096, 3072] fp16 out
    mma_gemm<0, true><<<dim3(24, 16), 512, G_SMEM>>>(
        xr, DD, WpackT, DD, QKV, 3 * DD, bpack, DD);

    // fused attention: scores + mask + softmax + P@V (fp16 mma, fp32 out)
    flash_attn<<<dim3(16, 32), 256, FA_SMEM>>>(QKV, mask, attn);

    // x1 = x + LN1(attn), with W1/W2 transposes riding along
    add_ln_prep<<<12288, 256>>>(x, attn, alpha1, beta1, x1, x1r, W1, W2);

    // FFN1: relu(x1r @ W1 + b1) fp16 out
    mma_gemm<1, true><<<dim3(32, 16), 512, G_SMEM>>>(
        x1r, DD, W1T, DD, h1, DFF, b1, DD);

    // FFN2: h1 @ W2 + b2  fp32 out
    mma_gemm<0, false><<<dim3(8, 16), 512, G_SMEM>>>(
        h1, DFF, W2T, DFF, ffn, DD, b2, DFF);

    // out = x1 + LN2(ffn)
    add_ln_final<<<MTOK, 256>>>(x1, ffn, alpha2, beta2, out);
}

// round 16
// speedup vs baseline: 1.0244x; 1.0068x over previous
#include <cuda_runtime.h>
#include <cuda_fp16.h>
#include <math.h>
#include <stdint.h>

#define BB 2
#define SS 2048
#define DD 1024
#define HH 16
#define DFF 4096
#define MTOK 4096

// ---------------- scratch (no allocations allowed) ----------------
__device__ __half g_xr[(size_t)MTOK * DD];           // fp16 x
__device__ __half g_WpackT[(size_t)3 * DD * DD];     // [3D, D] K-major packed qkv weights
__device__ float  g_bpack[3 * DD];
__device__ __half g_W1T[(size_t)DFF * DD];           // [4D, D]
__device__ __half g_W2T[(size_t)DD * DFF];           // [D, 4D]
__device__ __half g_QKV[(size_t)MTOK * 3 * DD];      // [tok, 3D] fp16
__device__ float  g_attn[(size_t)MTOK * DD];
__device__ float  g_x1[(size_t)MTOK * DD];           // exact
__device__ __half g_x1r[(size_t)MTOK * DD];          // fp16
__device__ __half g_h1[(size_t)MTOK * DFF];          // fp16
__device__ float  g_ffn[(size_t)MTOK * DD];

// ---------------- helpers ----------------
__device__ __forceinline__ uint32_t smem_u32(const void* p) {
    uint32_t a;
    asm("{ .reg .u64 t; cvta.to.shared.u64 t, %1; cvt.u32.u64 %0, t; }" : "=r"(a) : "l"(p));
    return a;
}
__device__ __forceinline__ uint32_t packh2(float lo, float hi) {
    uint32_t u;
    asm("cvt.rn.f16x2.f32 %0, %1, %2;" : "=r"(u) : "f"(hi), "f"(lo));
    return u;
}
#define SWZ128(o) ((o) ^ (((o) >> 3) & 0x70))
#define CP16(dst, src) asm volatile("cp.async.cg.shared.global [%0], [%1], 16;" :: "r"(dst), "l"(src))
#define LDSM4(r0, r1, r2, r3, a) \
    asm volatile("ldmatrix.sync.aligned.m8n8.x4.shared.b16 {%0,%1,%2,%3}, [%4];" \
                 : "=r"(r0), "=r"(r1), "=r"(r2), "=r"(r3) : "r"(a))
#define LDSM4T(r0, r1, r2, r3, a) \
    asm volatile("ldmatrix.sync.aligned.m8n8.x4.trans.shared.b16 {%0,%1,%2,%3}, [%4];" \
                 : "=r"(r0), "=r"(r1), "=r"(r2), "=r"(r3) : "r"(a))

__device__ __forceinline__ void mma_f16(float* d, const uint32_t* a, uint32_t b0, uint32_t b1) {
    asm volatile(
        "mma.sync.aligned.m16n8k16.row.col.f32.f16.f16.f32 "
        "{%0,%1,%2,%3}, {%4,%5,%6,%7}, {%8,%9}, {%0,%1,%2,%3};"
        : "+f"(d[0]), "+f"(d[1]), "+f"(d[2]), "+f"(d[3])
        : "r"(a[0]), "r"(a[1]), "r"(a[2]), "r"(a[3]), "r"(b0), "r"(b1));
}

// ================= FLASH ATTENTION (fp16, 128 q-rows/CTA) — R8 structure, base-2 softmax =================
#define FK_BYTES 16384
#define FV_BYTES 16384
#define OFF_Q 0
#define OFF_K 16384
#define OFF_V 49152
#define OFF_M 81920
#define FA_SMEM 90112

__global__ void __launch_bounds__(256, 1)
flash_attn(const __half* __restrict__ QKV, const int* __restrict__ mask,
           float* __restrict__ out) {
    extern __shared__ char smem[];
    const uint32_t sb = smem_u32(smem);
    int tid = threadIdx.x, wid = tid >> 5, lid = tid & 31;
    int g = lid >> 2, tc = lid & 3;
    int qt = blockIdx.x, bh = blockIdx.y;
    int b = bh >> 4, h = bh & 15;
    int q0 = qt * 128;
    int wq0 = wid * 16;
    const __half* base = QKV + (size_t)b * SS * 3072 + h * 64;
    const float SC = 0.125f * 1.44269504088896340736f;   // (1/8) * log2(e): base-2 domain

    int rA = (lid & 7) + ((lid >> 3) & 1) * 8;
    int cA = lid >> 4;
    int rB = (lid & 7) + ((lid >> 4) & 1) * 8;
    int cB = (lid >> 3) & 1;

#pragma unroll
    for (int i = 0; i < 4; i++) {
        int q = tid + i * 256, r = q >> 3, c = q & 7;
        CP16(sb + OFF_Q + SWZ128(q * 16), base + (size_t)(q0 + r) * 3072 + c * 8);
    }
#pragma unroll
    for (int i = 0; i < 4; i++) {
        int q = tid + i * 256, r = q >> 3, c = q & 7;
        CP16(sb + OFF_K + SWZ128(q * 16), base + (size_t)r * 3072 + 1024 + c * 8);
    }
#pragma unroll
    for (int i = 0; i < 4; i++) {
        int q = tid + i * 256, r = q >> 3, c = q & 7;
        CP16(sb + OFF_V + SWZ128(q * 16), base + (size_t)r * 3072 + 2048 + c * 8);
    }
    asm volatile("cp.async.commit_group;" ::: "memory");
    int* msmem = (int*)(smem + OFF_M);
#pragma unroll
    for (int i = 0; i < 8; i++) {
        int idx = tid + i * 256;
        msmem[idx] = mask[b * SS + idx];
    }
    asm volatile("cp.async.wait_group 0;" ::: "memory");
    __syncthreads();

    uint32_t af[4][4];
#pragma unroll
    for (int s = 0; s < 4; s++) {
        uint32_t addr = sb + OFF_Q + SWZ128((wq0 + rA) * 128 + (2 * s + cA) * 16);
        LDSM4(af[s][0], af[s][1], af[s][2], af[s][3], addr);
    }

    float oacc[8][4];
#pragma unroll
    for (int i = 0; i < 8; i++)
#pragma unroll
        for (int j = 0; j < 4; j++) oacc[i][j] = 0.f;
    float l0 = 0.f, l1 = 0.f, m0 = -INFINITY, m1 = -INFINITY;

    for (int it = 0; it < 16; it++) {
        int buf = it & 1;
        if (it + 1 < 16) {
            int kv1 = (it + 1) * 128, nb = buf ^ 1;
#pragma unroll
            for (int i = 0; i < 4; i++) {
                int q = tid + i * 256, r = q >> 3, c = q & 7;
                CP16(sb + OFF_K + nb * FK_BYTES + SWZ128(q * 16),
                     base + (size_t)(kv1 + r) * 3072 + 1024 + c * 8);
            }
#pragma unroll
            for (int i = 0; i < 4; i++) {
                int q = tid + i * 256, r = q >> 3, c = q & 7;
                CP16(sb + OFF_V + nb * FV_BYTES + SWZ128(q * 16),
                     base + (size_t)(kv1 + r) * 3072 + 2048 + c * 8);
            }
            asm volatile("cp.async.commit_group;" ::: "memory");
        }
        if (it > 0) {
            if (it + 1 < 16) asm volatile("cp.async.wait_group 1;" ::: "memory");
            else             asm volatile("cp.async.wait_group 0;" ::: "memory");
            __syncthreads();
        }

        int kv0 = it * 128;
        uint32_t kb = sb + OFF_K + buf * FK_BYTES;
        uint32_t vb = sb + OFF_V + buf * FV_BYTES;

        float sacc[16][4];
#pragma unroll
        for (int i = 0; i < 16; i++)
#pragma unroll
            for (int j = 0; j < 4; j++) sacc[i][j] = 0.f;
#pragma unroll
        for (int np = 0; np < 8; np++) {
            int nrow = 16 * np + rB;
#pragma unroll
            for (int s = 0; s < 4; s++) {
                uint32_t bq[4];
                LDSM4(bq[0], bq[1], bq[2], bq[3],
                      kb + SWZ128(nrow * 128 + (2 * s + cB) * 16));
                mma_f16(sacc[2 * np],     af[s], bq[0], bq[1]);
                mma_f16(sacc[2 * np + 1], af[s], bq[2], bq[3]);
            }
        }

        float mt0 = -INFINITY, mt1 = -INFINITY;
#pragma unroll
        for (int nt = 0; nt < 16; nt++) {
            int c0 = kv0 + 8 * nt + 2 * tc;
            int mk0 = msmem[c0], mk1 = msmem[c0 + 1];
            float s0 = sacc[nt][0] * SC, s1 = sacc[nt][1] * SC;
            float s2 = sacc[nt][2] * SC, s3 = sacc[nt][3] * SC;
            if (mk0 == 0) { s0 = -INFINITY; s2 = -INFINITY; }
            if (mk1 == 0) { s1 = -INFINITY; s3 = -INFINITY; }
            sacc[nt][0] = s0; sacc[nt][1] = s1; sacc[nt][2] = s2; sacc[nt][3] = s3;
            mt0 = fmaxf(mt0, fmaxf(s0, s1));
            mt1 = fmaxf(mt1, fmaxf(s2, s3));
        }
        mt0 = fmaxf(mt0, __shfl_xor_sync(0xffffffff, mt0, 1));
        mt0 = fmaxf(mt0, __shfl_xor_sync(0xffffffff, mt0, 2));
        mt1 = fmaxf(mt1, __shfl_xor_sync(0xffffffff, mt1, 1));
        mt1 = fmaxf(mt1, __shfl_xor_sync(0xffffffff, mt1, 2));
        float mn0 = fmaxf(m0, mt0), mn1 = fmaxf(m1, mt1);
        float al0 = exp2f(m0 - mn0), al1 = exp2f(m1 - mn1);
        l0 *= al0; l1 *= al1;
#pragma unroll
        for (int i = 0; i < 8; i++) {
            oacc[i][0] *= al0; oacc[i][1] *= al0;
            oacc[i][2] *= al1; oacc[i][3] *= al1;
        }
#pragma unroll
        for (int nt = 0; nt < 16; nt++) {
            float p0 = exp2f(sacc[nt][0] - mn0);
            float p1 = exp2f(sacc[nt][1] - mn0);
            float p2 = exp2f(sacc[nt][2] - mn1);
            float p3 = exp2f(sacc[nt][3] - mn1);
            l0 += p0 + p1; l1 += p2 + p3;
            sacc[nt][0] = p0; sacc[nt][1] = p1;
            sacc[nt][2] = p2; sacc[nt][3] = p3;
        }
        m0 = mn0; m1 = mn1;

#pragma unroll
        for (int kc = 0; kc < 8; kc++) {
            uint32_t afr[4];
            afr[0] = packh2(sacc[2 * kc][0],     sacc[2 * kc][1]);
            afr[1] = packh2(sacc[2 * kc][2],     sacc[2 * kc][3]);
            afr[2] = packh2(sacc[2 * kc + 1][0], sacc[2 * kc + 1][1]);
            afr[3] = packh2(sacc[2 * kc + 1][2], sacc[2 * kc + 1][3]);
            int vrow = 16 * kc + rA;
#pragma unroll
            for (int np = 0; np < 4; np++) {
                uint32_t bv[4];
                LDSM4T(bv[0], bv[1], bv[2], bv[3],
                       vb + SWZ128(vrow * 128 + np * 32 + cA * 16));
                mma_f16(oacc[2 * np],     afr, bv[0], bv[1]);
                mma_f16(oacc[2 * np + 1], afr, bv[2], bv[3]);
            }
        }
        __syncthreads();
    }

    l0 += __shfl_xor_sync(0xffffffff, l0, 1);
    l0 += __shfl_xor_sync(0xffffffff, l0, 2);
    l1 += __shfl_xor_sync(0xffffffff, l1, 1);
    l1 += __shfl_xor_sync(0xffffffff, l1, 2);

    float il0 = 1.f / l0, il1 = 1.f / l1;
    int r0 = q0 + wq0 + g, r1 = r0 + 8;
    float* o0 = out + (size_t)(b * SS + r0) * DD + h * 64 + 2 * tc;
    float* o1 = out + (size_t)(b * SS + r1) * DD + h * 64 + 2 * tc;
#pragma unroll
    for (int nt = 0; nt < 8; nt++) {
        *(float2*)(o0 + nt * 8) = make_float2(oacc[nt][0] * il0, oacc[nt][1] * il0);
        *(float2*)(o1 + nt * 8) = make_float2(oacc[nt][2] * il1, oacc[nt][3] * il1);
    }
}

// ---------------- fp16 mma GEMM: 256x128 tile, BK=64, 512 threads, 4-stage ----------------
#define GA_BYTES 32768
#define GB_BYTES 16384
#define G_SMEM (4 * (GA_BYTES + GB_BYTES))

template <int MODE, bool WH>
__global__ void __launch_bounds__(512)
mma_gemm(const __half* __restrict__ A, int lda,
         const __half* __restrict__ B, int ldb,
         void* __restrict__ Cv, int ldc,
         const float* __restrict__ bias, int K) {
    extern __shared__ char smem[];
    const uint32_t sb = smem_u32(smem);
    int tid = threadIdx.x, wid = tid >> 5, lid = tid & 31;
    int m0 = blockIdx.y * 256, n0 = blockIdx.x * 128;
    int wm0 = (wid >> 2) * 64, wn0 = (wid & 3) * 32;

    int rA = (lid & 7) + ((lid >> 3) & 1) * 8;
    int cA = lid >> 4;
    int rB = (lid & 7) + ((lid >> 4) & 1) * 8;
    int cB = (lid >> 3) & 1;

    float acc[4][4][4];
#pragma unroll
    for (int i = 0; i < 4; i++)
#pragma unroll
        for (int j = 0; j < 4; j++)
#pragma unroll
            for (int r = 0; r < 4; r++) acc[i][j][r] = 0.f;

    const int NC = K >> 6;

#pragma unroll
    for (int pc = 0; pc < 3; pc++) {
        int k0 = pc << 6;
        uint32_t ab = sb + pc * GA_BYTES;
        uint32_t bb = sb + 4 * GA_BYTES + pc * GB_BYTES;
#pragma unroll
        for (int i = 0; i < 4; i++) {
            int q = tid + i * 512, row = q >> 3, cg = q & 7;
            CP16(ab + SWZ128(q * 16), A + (size_t)(m0 + row) * lda + k0 + cg * 8);
        }
#pragma unroll
        for (int i = 0; i < 2; i++) {
            int q = tid + i * 512, row = q >> 3, cg = q & 7;
            CP16(bb + SWZ128(q * 16), B + (size_t)(n0 + row) * ldb + k0 + cg * 8);
        }
        asm volatile("cp.async.commit_group;" ::: "memory");
    }

    for (int c = 0; c < NC; c++) {
        int slot = c & 3;
        int rem = NC - 1 - c;
        if (rem >= 2)      asm volatile("cp.async.wait_group 2;" ::: "memory");
        else if (rem == 1) asm volatile("cp.async.wait_group 1;" ::: "memory");
        else               asm volatile("cp.async.wait_group 0;" ::: "memory");
        __syncthreads();

        if (c + 3 < NC) {
            int k0 = (c + 3) << 6;
            int lb = (c + 3) & 3;
            uint32_t ab = sb + lb * GA_BYTES;
            uint32_t bb = sb + 4 * GA_BYTES + lb * GB_BYTES;
#pragma unroll
            for (int i = 0; i < 4; i++) {
                int q = tid + i * 512, row = q >> 3, cg = q & 7;
                CP16(ab + SWZ128(q * 16), A + (size_t)(m0 + row) * lda + k0 + cg * 8);
            }
#pragma unroll
            for (int i = 0; i < 2; i++) {
                int q = tid + i * 512, row = q >> 3, cg = q & 7;
                CP16(bb + SWZ128(q * 16), B + (size_t)(n0 + row) * ldb + k0 + cg * 8);
            }
            asm volatile("cp.async.commit_group;" ::: "memory");
        }

        uint32_t ab = sb + slot * GA_BYTES;
        uint32_t bb = sb + 4 * GA_BYTES + slot * GB_BYTES;
#pragma unroll
        for (int s = 0; s < 4; s++) {
            uint32_t af[4][4];
#pragma unroll
            for (int mt = 0; mt < 4; mt++) {
                int row = wm0 + mt * 16 + rA;
                LDSM4(af[mt][0], af[mt][1], af[mt][2], af[mt][3],
                      ab + SWZ128(row * 128 + (2 * s + cA) * 16));
            }
            uint32_t bfr[8];
#pragma unroll
            for (int pr = 0; pr < 2; pr++) {
                int row = wn0 + pr * 16 + rB;
                LDSM4(bfr[4 * pr], bfr[4 * pr + 1], bfr[4 * pr + 2], bfr[4 * pr + 3],
                      bb + SWZ128(row * 128 + (2 * s + cB) * 16));
            }
#pragma unroll
            for (int mt = 0; mt < 4; mt++) {
#pragma unroll
                for (int nt = 0; nt < 4; nt++)
                    mma_f16(acc[mt][nt], af[mt], bfr[2 * nt], bfr[2 * nt + 1]);
            }
        }
    }

    int g = lid >> 2, tc = lid & 3;
#pragma unroll
    for (int mt = 0; mt < 4; mt++) {
        int row = m0 + wm0 + mt * 16 + g;
#pragma unroll
        for (int nt = 0; nt < 4; nt++) {
            int col = n0 + wn0 + nt * 8 + tc * 2;
            float v00 = acc[mt][nt][0], v01 = acc[mt][nt][1];
            float v10 = acc[mt][nt][2], v11 = acc[mt][nt][3];
            float2 bv = *(const float2*)(bias + col);
            v00 += bv.x; v01 += bv.y; v10 += bv.x; v11 += bv.y;
            if (MODE == 1) {
                v00 = fmaxf(v00, 0.f); v01 = fmaxf(v01, 0.f);
                v10 = fmaxf(v10, 0.f); v11 = fmaxf(v11, 0.f);
            }
            if (WH) {
                __half* C = (__half*)Cv;
                *(uint32_t*)(C + (size_t)row * ldc + col) = packh2(v00, v01);
                *(uint32_t*)(C + (size_t)(row + 8) * ldc + col) = packh2(v10, v11);
            } else {
                float* C = (float*)Cv;
                *(float2*)(C + (size_t)row * ldc + col) = make_float2(v00, v01);
                *(float2*)(C + (size_t)(row + 8) * ldc + col) = make_float2(v10, v11);
            }
        }
    }
}

// ---------------- fused prep (QKV-path only): round_copy | pack_bias | pack_wT ----------------
__global__ void prep_all(const float* __restrict__ x,
                         const float* __restrict__ Wq, const float* __restrict__ Wk,
                         const float* __restrict__ Wv,
                         const float* __restrict__ bq, const float* __restrict__ bk,
                         const float* __restrict__ bv) {
    __shared__ float t[32][33];
    int bid = blockIdx.x;
    int tid = threadIdx.x;
    int tx = tid & 31, ty = tid >> 5;

    if (bid < 4096) {
        int i = bid * 256 + tid;
        float4 v = ((const float4*)x)[i];
        uint32_t* o = (uint32_t*)g_xr;
        o[2 * i]     = packh2(v.x, v.y);
        o[2 * i + 1] = packh2(v.z, v.w);
    } else if (bid < 4108) {
        int i = (bid - 4096) * 256 + tid;
        if (i < 3 * DD) {
            int which = i / DD, c = i % DD;
            const float* b = (which == 0) ? bq : (which == 1) ? bk : bv;
            g_bpack[i] = b[c];
        }
    } else {
        int z = bid - 4108;
        int bx = z & 31;
        int by = (z >> 5) & 1;
        int bz = z >> 6;
        int which = bz / HH, h = bz % HH;
        const float* W = (which == 0) ? Wq : (which == 1) ? Wk : Wv;
        int d0 = bx * 32, e0 = by * 32;
#pragma unroll
        for (int i = 0; i < 32; i += 8)
            t[ty + i][tx] = W[(size_t)h * (DD * 64) + (size_t)(d0 + ty + i) * 64 + e0 + tx];
        __syncthreads();
#pragma unroll
        for (int i = 0; i < 32; i += 8)
            g_WpackT[(size_t)(which * DD + h * 64 + e0 + ty + i) * DD + d0 + tx] =
                __float2half_rn(t[tx][ty + i]);
    }
}

// ---------------- add_ln (block-per-row) fused with W1/W2 transposes ----------------
__global__ void add_ln_prep(const float* __restrict__ xres, const float* __restrict__ a,
                            const float* __restrict__ alpha, const float* __restrict__ beta,
                            float* __restrict__ out, __half* __restrict__ outr,
                            const float* __restrict__ W1, const float* __restrict__ W2) {
    __shared__ float shm[32][33];
    int bid = blockIdx.x;
    int tid = threadIdx.x;

    if (bid < 4096) {
        int row = bid;
        int wid = tid >> 5, lid = tid & 31;
        float4 v = ((const float4*)(a + (size_t)row * DD))[tid];
        float s  = (v.x + v.y) + (v.z + v.w);
        float sq = v.x * v.x + v.y * v.y + v.z * v.z + v.w * v.w;
#pragma unroll
        for (int o = 16; o > 0; o >>= 1) {
            s  += __shfl_xor_sync(0xffffffff, s, o);
            sq += __shfl_xor_sync(0xffffffff, sq, o);
        }
        float* red = &shm[0][0];
        if (lid == 0) { red[wid] = s; red[wid + 8] = sq; }
        __syncthreads();
        if (tid < 8) {
            float ws = red[tid], wq = red[tid + 8];
#pragma unroll
            for (int o = 4; o > 0; o >>= 1) {
                ws += __shfl_xor_sync(0xff, ws, o);
                wq += __shfl_xor_sync(0xff, wq, o);
            }
            if (tid == 0) { red[0] = ws; red[1] = wq; }
        }
        __syncthreads();
        float S = red[0], SQ = red[1];
        float mean = S * (1.f / DD);
        float var = (SQ - (float)DD * mean * mean) * (1.f / (DD - 1));
        float inv = 1.f / (sqrtf(fmaxf(var, 0.f)) + 1e-6f);

        float4 xr4 = ((const float4*)(xres + (size_t)row * DD))[tid];
        float4 al4 = ((const float4*)alpha)[tid];
        float4 be4 = ((const float4*)beta)[tid];
        float4 o4;
        o4.x = xr4.x + al4.x * (v.x - mean) * inv + be4.x;
        o4.y = xr4.y + al4.y * (v.y - mean) * inv + be4.y;
        o4.z = xr4.z + al4.z * (v.z - mean) * inv + be4.z;
        o4.w = xr4.w + al4.w * (v.w - mean) * inv + be4.w;
        ((float4*)(out + (size_t)row * DD))[tid] = o4;
        uint32_t* oh = (uint32_t*)(outr + (size_t)row * DD);
        oh[2 * tid]     = packh2(o4.x, o4.y);
        oh[2 * tid + 1] = packh2(o4.z, o4.w);
    } else if (bid < 8192) {
        int z = bid - 4096;
        int tx = tid & 31, ty = tid >> 5;
        int bx = z & 127;
        int by = z >> 7;
        int c0 = bx * 32, r0 = by * 32;
#pragma unroll
        for (int i = 0; i < 32; i += 8)
            shm[ty + i][tx] = W1[(size_t)(r0 + ty + i) * DFF + c0 + tx];
        __syncthreads();
#pragma unroll
        for (int i = 0; i < 32; i += 8)
            g_W1T[(size_t)(c0 + ty + i) * DD + r0 + tx] = __float2half_rn(shm[tx][ty + i]);
    } else {
        int z = bid - 8192;
        int tx = tid & 31, ty = tid >> 5;
        int bx = z & 31;
        int by = z >> 5;
        int c0 = bx * 32, r0 = by * 32;
#pragma unroll
        for (int i = 0; i < 32; i += 8)
            shm[ty + i][tx] = W2[(size_t)(r0 + ty + i) * DD + c0 + tx];
        __syncthreads();
#pragma unroll
        for (int i = 0; i < 32; i += 8)
            g_W2T[(size_t)(c0 + ty + i) * DFF + r0 + tx] = __float2half_rn(shm[tx][ty + i]);
    }
}

// ---------------- plain add_ln (block-per-row), final LN ----------------
__global__ void add_ln_final(const float* __restrict__ xres, const float* __restrict__ a,
                             const float* __restrict__ alpha, const float* __restrict__ beta,
                             float* __restrict__ out) {
    int row = blockIdx.x;
    int tid = threadIdx.x;
    int wid = tid >> 5, lid = tid & 31;

    float4 v = ((const float4*)(a + (size_t)row * DD))[tid];
    float s  = (v.x + v.y) + (v.z + v.w);
    float sq = v.x * v.x + v.y * v.y + v.z * v.z + v.w * v.w;
#pragma unroll
    for (int o = 16; o > 0; o >>= 1) {
        s  += __shfl_xor_sync(0xffffffff, s, o);
        sq += __shfl_xor_sync(0xffffffff, sq, o);
    }
    __shared__ float red[16];
    if (lid == 0) { red[wid] = s; red[wid + 8] = sq; }
    __syncthreads();
    if (tid < 8) {
        float ws = red[tid], wq = red[tid + 8];
#pragma unroll
        for (int o = 4; o > 0; o >>= 1) {
            ws += __shfl_xor_sync(0xff, ws, o);
            wq += __shfl_xor_sync(0xff, wq, o);
        }
        if (tid == 0) { red[0] = ws; red[1] = wq; }
    }
    __syncthreads();
    float S = red[0], SQ = red[1];
    float mean = S * (1.f / DD);
    float var = (SQ - (float)DD * mean * mean) * (1.f / (DD - 1));
    float inv = 1.f / (sqrtf(fmaxf(var, 0.f)) + 1e-6f);

    float4 xr4 = ((const float4*)(xres + (size_t)row * DD))[tid];
    float4 al4 = ((const float4*)alpha)[tid];
    float4 be4 = ((const float4*)beta)[tid];
    float4 o4;
    o4.x = xr4.x + al4.x * (v.x - mean) * inv + be4.x;
    o4.y = xr4.y + al4.y * (v.y - mean) * inv + be4.y;
    o4.z = xr4.z + al4.z * (v.z - mean) * inv + be4.z;
    o4.w = xr4.w + al4.w * (v.w - mean) * inv + be4.w;
    ((float4*)(out + (size_t)row * DD))[tid] = o4;
}

// ---------------- launch ----------------
extern "C" void kernel_launch(void* const* d_in, const int* in_sizes, int n_in,
                              void* d_out, int out_size) {
    const float* x      = (const float*)d_in[0];
    const int*   mask   = (const int*)d_in[1];
    const float* Wq     = (const float*)d_in[2];
    const float* bq     = (const float*)d_in[3];
    const float* Wk     = (const float*)d_in[4];
    const float* bk     = (const float*)d_in[5];
    const float* Wv     = (const float*)d_in[6];
    const float* bv     = (const float*)d_in[7];
    const float* W1     = (const float*)d_in[8];
    const float* b1     = (const float*)d_in[9];
    const float* W2     = (const float*)d_in[10];
    const float* b2     = (const float*)d_in[11];
    const float* alpha1 = (const float*)d_in[12];
    const float* beta1  = (const float*)d_in[13];
    const float* alpha2 = (const float*)d_in[14];
    const float* beta2  = (const float*)d_in[15];
    float* out = (float*)d_out;

    __half *xr, *WpackT, *W1T, *W2T, *QKV, *x1r, *h1;
    float *bpack, *attn, *x1, *ffn;
    cudaGetSymbolAddress((void**)&xr,     g_xr);
    cudaGetSymbolAddress((void**)&WpackT, g_WpackT);
    cudaGetSymbolAddress((void**)&bpack,  g_bpack);
    cudaGetSymbolAddress((void**)&W1T,    g_W1T);
    cudaGetSymbolAddress((void**)&W2T,    g_W2T);
    cudaGetSymbolAddress((void**)&QKV,    g_QKV);
    cudaGetSymbolAddress((void**)&attn,   g_attn);
    cudaGetSymbolAddress((void**)&x1,     g_x1);
    cudaGetSymbolAddress((void**)&x1r,    g_x1r);
    cudaGetSymbolAddress((void**)&h1,     g_h1);
    cudaGetSymbolAddress((void**)&ffn,    g_ffn);

    cudaFuncSetAttribute(mma_gemm<0, true>,  cudaFuncAttributeMaxDynamicSharedMemorySize, G_SMEM);
    cudaFuncSetAttribute(mma_gemm<1, true>,  cudaFuncAttributeMaxDynamicSharedMemorySize, G_SMEM);
    cudaFuncSetAttribute(mma_gemm<0, false>, cudaFuncAttributeMaxDynamicSharedMemorySize, G_SMEM);
    cudaFuncSetAttribute(flash_attn, cudaFuncAttributeMaxDynamicSharedMemorySize, FA_SMEM);

    // prep for QKV path only (x round, bias pack, Wqkv pack)
    prep_all<<<7180, 256>>>(x, Wq, Wk, Wv, bq, bk, bv);

    // QKV = xr @ WpackT^T + bias  [4096, 3072] fp16 out
    mma_gemm<0, true><<<dim3(24, 16), 512, G_SMEM>>>(
        xr, DD, WpackT, DD, QKV, 3 * DD, bpack, DD);

    // fused attention: scores + mask + softmax + P@V (fp16 mma, fp32 out)
    flash_attn<<<dim3(16, 32), 256, FA_SMEM>>>(QKV, mask, attn);

    // x1 = x + LN1(attn), with W1/W2 transposes riding along
    add_ln_prep<<<12288, 256>>>(x, attn, alpha1, beta1, x1, x1r, W1, W2);

    // FFN1: relu(x1r @ W1 + b1) fp16 out
    mma_gemm<1, true><<<dim3(32, 16), 512, G_SMEM>>>(
        x1r, DD, W1T, DD, h1, DFF, b1, DD);

    // FFN2: h1 @ W2 + b2  fp32 out
    mma_gemm<0, false><<<dim3(8, 16), 512, G_SMEM>>>(
        h1, DFF, W2T, DFF, ffn, DD, b2, DFF);

    // out = x1 + LN2(ffn)
    add_ln_final<<<MTOK, 256>>>(x1, ffn, alpha2, beta2, out);
}